// round 2
// baseline (speedup 1.0000x reference)
#include <cuda_runtime.h>
#include <cuda_bf16.h>
#include <math_constants.h>
#include <cub/cub.cuh>

// ---------------------------------------------------------------------------
// Problem constants
// ---------------------------------------------------------------------------
#define HH 64
#define WWID 64
#define CIN 512
#define NB 2
#define NANCH 9
#define ATOT (HH*WWID*NANCH)      // 36864
#define NPRE 6000
#define NPOST 300
#define MASKW 94                  // ceil(6000/64)
#define NMS_T 0.7f

// Output layout (float32, concatenated in reference return order)
#define OFF_LOCS   0
#define OFF_SCORES (NB*ATOT*4)                 // 294912
#define OFF_ROIS   (OFF_SCORES + NB*ATOT*2)    // 442368
#define OFF_RIDX   (OFF_ROIS + NB*NPOST*4)     // 444768
#define OFF_ANCHOR (OFF_RIDX + NB*NPOST)       // 445368
#define OFF_VMASK  (OFF_ANCHOR + ATOT*4)       // 592824

// ---------------------------------------------------------------------------
// Scratch (static __device__ arrays — allocation-free)
// ---------------------------------------------------------------------------
__device__ float g_h[NB*CIN*HH*WWID];            // conv output (16 MB)
__device__ float g_wt[CIN*CIN*9];                // transposed weights [c][tap][k]
__device__ float g_score[NB*ATOT];               // fg score or -inf
__device__ float g_keys_out[NB*ATOT];
__device__ int   g_idx_in[ATOT];
__device__ int   g_idx_out[NB*ATOT];
__device__ float4 g_roi[NB*ATOT];
__device__ float4 g_boxes[NB*NPRE];
__device__ float g_boxsc[NB*NPRE];
__device__ unsigned long long g_mask[(size_t)NB*NPRE*MASKW];
__device__ int g_kept[NB*NPOST];
__device__ int g_keptcnt[NB];
__device__ __align__(256) unsigned char g_cub_temp[8<<20];

// ---------------------------------------------------------------------------
// Weight transpose: w[k][c][tap] -> g_wt[c][tap][k]
// ---------------------------------------------------------------------------
__global__ void wt_kernel(const float* __restrict__ w) {
    int e = blockIdx.x*256 + threadIdx.x;
    if (e >= CIN*CIN*9) return;
    int tap = e % 9;
    int c   = (e/9) % CIN;
    int k   = e/(9*CIN);
    g_wt[((size_t)c*9 + tap)*CIN + k] = w[e];
}

// ---------------------------------------------------------------------------
// 3x3 conv + bias + ReLU.  grid (8 kblk, 64 rows, 2 n), block 256.
// Block computes 64 out-channels x 64 pixels (one row). 8-channel smem chunks.
// ---------------------------------------------------------------------------
__global__ __launch_bounds__(256) void conv_kernel(const float* __restrict__ x,
                                                   const float* __restrict__ bias) {
    __shared__ float s_in[8][3][68];   // padded row stride
    __shared__ float s_w[8][9][64];

    int n  = blockIdx.z;
    int y  = blockIdx.y;
    int k0 = blockIdx.x*64;
    int tid = threadIdx.x;
    int tx = tid & 15, ty = tid >> 4;
    int px0 = tx*4;

    float acc[4][4];
#pragma unroll
    for (int a=0;a<4;a++)
#pragma unroll
        for (int b2=0;b2<4;b2++) acc[a][b2]=0.f;

    const float* xin = x + (size_t)n*CIN*HH*WWID;

    for (int c0=0; c0<CIN; c0+=8) {
        // input patch: 8 ch x 3 rows x 66 cols (zero halo)
        for (int e=tid; e<8*3*66; e+=256) {
            int cc = e/198;
            int r  = e%198;
            int ry = r/66;
            int j  = r%66;
            int yy = y+ry-1, xx = j-1;
            float v = 0.f;
            if (yy>=0 && yy<HH && xx>=0 && xx<WWID)
                v = xin[((size_t)(c0+cc)*HH+yy)*WWID+xx];
            s_in[cc][ry][j] = v;
        }
        // weights: 8 ch x 9 taps x 64 outch (coalesced from g_wt)
        for (int e=tid; e<8*9*64; e+=256) {
            int kk = e & 63;
            int tap = (e>>6)%9;
            int cc = e/576;
            s_w[cc][tap][kk] = g_wt[((size_t)(c0+cc)*9 + tap)*CIN + k0 + kk];
        }
        __syncthreads();

#pragma unroll
        for (int cc=0; cc<8; cc++) {
            float a[3][6];
#pragma unroll
            for (int ry=0; ry<3; ry++) {
                float4 v4 = *(const float4*)&s_in[cc][ry][px0];
                a[ry][0]=v4.x; a[ry][1]=v4.y; a[ry][2]=v4.z; a[ry][3]=v4.w;
                a[ry][4]=s_in[cc][ry][px0+4];
                a[ry][5]=s_in[cc][ry][px0+5];
            }
#pragma unroll
            for (int dy=0; dy<3; dy++)
#pragma unroll
            for (int dx=0; dx<3; dx++) {
                float4 wv = *(const float4*)&s_w[cc][dy*3+dx][ty*4];
#pragma unroll
                for (int p=0; p<4; p++) {
                    float iv = a[dy][p+dx];
                    acc[0][p] = fmaf(wv.x, iv, acc[0][p]);
                    acc[1][p] = fmaf(wv.y, iv, acc[1][p]);
                    acc[2][p] = fmaf(wv.z, iv, acc[2][p]);
                    acc[3][p] = fmaf(wv.w, iv, acc[3][p]);
                }
            }
        }
        __syncthreads();
    }

#pragma unroll
    for (int ch=0; ch<4; ch++) {
        int k = k0 + ty*4 + ch;
        float bv = bias[k];
        float* outp = &g_h[(((size_t)n*CIN + k)*HH + y)*WWID + px0];
#pragma unroll
        for (int p=0; p<4; p++) outp[p] = fmaxf(acc[ch][p]+bv, 0.f);
    }
}

// ---------------------------------------------------------------------------
// Anchor (matches numpy _anchor_base + integer shift: f32 base, f64 add, f32 out)
// ---------------------------------------------------------------------------
__device__ __forceinline__ void anchor_calc(int y, int x, int k,
                                            float& o0, float& o1, float& o2, float& o3) {
    const double ratios[3] = {0.5, 1.0, 2.0};
    const double scales[3] = {8.0, 16.0, 32.0};
    int i = k/3, j = k%3;
    double h = 16.0*scales[j]*sqrt(ratios[i]);
    double w = 16.0*scales[j]*sqrt(1.0/ratios[i]);
    float b0 = (float)(8.0 - h*0.5);
    float b1 = (float)(8.0 - w*0.5);
    float b2 = (float)(8.0 + h*0.5);
    float b3 = (float)(8.0 + w*0.5);
    o0 = (float)((double)b0 + (double)(y*16));
    o1 = (float)((double)b1 + (double)(x*16));
    o2 = (float)((double)b2 + (double)(y*16));
    o3 = (float)((double)b3 + (double)(x*16));
}

__device__ __forceinline__ float load_dim(const void* p) {
    int iv = *(const int*)p;
    if (iv > 0 && iv < (1<<20)) return (float)iv;  // int32 scalar
    return *(const float*)p;                        // fallback: float scalar
}

// ---------------------------------------------------------------------------
// Heads: 1x1 score(18)+loc(36) conv, softmax fg, anchors, decode+clip+validity.
// grid (64 rows, 2 n), block 256 (64 px x 4 output-groups).
// ---------------------------------------------------------------------------
__global__ __launch_bounds__(256) void heads_kernel(const float* __restrict__ sw,
                                                    const float* __restrict__ sb,
                                                    const float* __restrict__ lw,
                                                    const float* __restrict__ lb,
                                                    const void* ihp, const void* iwp,
                                                    float* __restrict__ out) {
    __shared__ float s_h[32][64];
    __shared__ float s_w2[54][32];
    __shared__ float s_o[54][64];

    int y = blockIdx.x, n = blockIdx.y;
    int tid = threadIdx.x;
    int px = tid & 63, og = tid >> 6;

    float acc[14];
#pragma unroll
    for (int t=0;t<14;t++) acc[t]=0.f;

    for (int c0=0; c0<CIN; c0+=32) {
        for (int e=tid; e<2048; e+=256) {
            int cc = e>>6, p = e&63;
            s_h[cc][p] = g_h[(((size_t)n*CIN + c0+cc)*HH + y)*WWID + p];
        }
        for (int e=tid; e<1728; e+=256) {
            int o = e>>5, cc = e&31;
            s_w2[o][cc] = (o<18) ? sw[o*CIN + c0+cc] : lw[(o-18)*CIN + c0+cc];
        }
        __syncthreads();
#pragma unroll 8
        for (int cc=0; cc<32; cc++) {
            float hv = s_h[cc][px];
#pragma unroll
            for (int t=0; t<14; t++) {
                int o = og + 4*t;
                if (o < 54) acc[t] = fmaf(s_w2[o][cc], hv, acc[t]);
            }
        }
        __syncthreads();
    }

    int pix = y*64 + px;
#pragma unroll
    for (int t=0; t<14; t++) {
        int o = og + 4*t;
        if (o < 54) {
            float v = acc[t] + ((o<18) ? sb[o] : lb[o-18]);
            s_o[o][px] = v;
            if (o < 18)
                out[OFF_SCORES + ((size_t)n*ATOT + (size_t)pix*9 + (o>>1))*2 + (o&1)] = v;
            else {
                int c = o-18;
                out[OFF_LOCS + ((size_t)n*ATOT + (size_t)pix*9 + (c>>2))*4 + (c&3)] = v;
            }
        }
    }
    __syncthreads();

    float img_h = load_dim(ihp), img_w = load_dim(iwp);

    for (int e=tid; e<576; e+=256) {
        int p2 = e & 63;
        int k  = e >> 6;       // covers k=0,1 for all px; k strided below
        // 576 elems / 256 threads: need second pass handling
        // (e loop covers all 9*64=576 anchor-pixel pairs)
        float s0 = s_o[2*k][p2], s1 = s_o[2*k+1][p2];
        float m  = fmaxf(s0,s1);
        float e0 = expf(s0-m), e1 = expf(s1-m);
        float fg = e1/(e0+e1);

        float d0 = s_o[18+4*k+0][p2];
        float d1 = s_o[18+4*k+1][p2];
        float d2 = s_o[18+4*k+2][p2];
        float d3 = s_o[18+4*k+3][p2];

        float a0,a1,a2,a3;
        anchor_calc(y, p2, k, a0,a1,a2,a3);

        float ah = a2-a0, aw = a3-a1;
        float acy = a0 + 0.5f*ah, acx = a1 + 0.5f*aw;
        float cy = fmaf(d0, ah, acy);
        float cx = fmaf(d1, aw, acx);
        float h  = expf(d2)*ah;
        float w  = expf(d3)*aw;
        float r0 = fminf(fmaxf(cy-0.5f*h, 0.f), img_h);
        float r1 = fminf(fmaxf(cx-0.5f*w, 0.f), img_w);
        float r2 = fminf(fmaxf(cy+0.5f*h, 0.f), img_h);
        float r3 = fminf(fmaxf(cx+0.5f*w, 0.f), img_w);
        bool valid = (r2-r0 >= 16.f) && (r3-r1 >= 16.f);

        int aidx = (y*64 + p2)*9 + k;
        g_score[n*ATOT + aidx] = valid ? fg : -CUDART_INF_F;
        g_roi[(size_t)n*ATOT + aidx] = make_float4(r0,r1,r2,r3);
        g_idx_in[aidx] = aidx;
        if (n == 0) {
            out[OFF_ANCHOR + (size_t)aidx*4 + 0] = a0;
            out[OFF_ANCHOR + (size_t)aidx*4 + 1] = a1;
            out[OFF_ANCHOR + (size_t)aidx*4 + 2] = a2;
            out[OFF_ANCHOR + (size_t)aidx*4 + 3] = a3;
        }
    }
}

// ---------------------------------------------------------------------------
// Gather top-6000 boxes + scores after sort
// ---------------------------------------------------------------------------
__global__ void gather_kernel() {
    int t = blockIdx.x*256 + threadIdx.x;
    if (t >= NB*NPRE) return;
    int n = t/NPRE, i = t%NPRE;
    int idx = g_idx_out[n*ATOT + i];
    g_boxes[t] = g_roi[(size_t)n*ATOT + idx];
    g_boxsc[t] = g_keys_out[n*ATOT + i];
}

// ---------------------------------------------------------------------------
// NMS bitmask: 64x64 tile per block. grid (94 jb, 94 ib, 2 n), block 64.
// ---------------------------------------------------------------------------
__global__ __launch_bounds__(64) void mask_kernel() {
    int n  = blockIdx.z;
    int jb = blockIdx.x;
    int ib = blockIdx.y;
    int t  = threadIdx.x;

    __shared__ float4 cb[64];
    int j = jb*64 + t;
    cb[t] = (j < NPRE) ? g_boxes[n*NPRE + j] : make_float4(0.f,0.f,0.f,0.f);
    __syncthreads();

    int i = ib*64 + t;
    if (i >= NPRE) return;
    float4 bi = g_boxes[n*NPRE + i];
    float areai = (bi.z-bi.x)*(bi.w-bi.y);

    unsigned long long word = 0ull;
    int jmax = min(64, NPRE - jb*64);
    for (int jj=0; jj<jmax; jj++) {
        float4 bj = cb[jj];
        float areaj = (bj.z-bj.x)*(bj.w-bj.y);
        float ih = fmaxf(fminf(bi.z,bj.z) - fmaxf(bi.x,bj.x), 0.f);
        float iw = fmaxf(fminf(bi.w,bj.w) - fmaxf(bi.y,bj.y), 0.f);
        float inter = ih*iw;
        float iou = inter/(areai + areaj - inter + 1e-9f);
        if (iou > NMS_T) word |= (1ull << jj);
    }
    g_mask[((size_t)n*NPRE + i)*MASKW + jb] = word;
}

// ---------------------------------------------------------------------------
// Greedy NMS scan: one warp per batch, register-resident suppression state.
// ---------------------------------------------------------------------------
__global__ void scan_kernel() {
    int n = blockIdx.x;
    int lane = threadIdx.x;
    const unsigned FULL = 0xffffffffu;

    unsigned long long r0=0ull, r1=0ull, r2=0ull;   // words lane, lane+32, lane+64
    int cnt = 0;
    const unsigned long long* mk = g_mask + (size_t)n*NPRE*MASKW;
    const float* sc = g_boxsc + n*NPRE;

    for (int ch=0; ch<MASKW; ch++) {
        int i0 = ch*64 + lane, i1 = i0 + 32;
        unsigned long long m0 = (i0 < NPRE) ? mk[(size_t)i0*MASKW + ch] : 0ull;
        unsigned long long m1 = (i1 < NPRE) ? mk[(size_t)i1*MASKW + ch] : 0ull;
        float s0 = (i0 < NPRE) ? sc[i0] : -CUDART_INF_F;
        float s1 = (i1 < NPRE) ? sc[i1] : -CUDART_INF_F;
        unsigned inv0 = __ballot_sync(FULL, !isfinite(s0));
        unsigned inv1 = __ballot_sync(FULL, !isfinite(s1));
        unsigned long long W = (unsigned long long)inv0 | ((unsigned long long)inv1 << 32);

        int seg = ch >> 5, ln = ch & 31;
        unsigned long long rr = (seg==0) ? r0 : ((seg==1) ? r1 : r2);
        W |= __shfl_sync(FULL, rr, ln);

        unsigned long long keptb = 0ull;
        while (~W) {
            int p = __ffsll((long long)(~W)) - 1;
            keptb |= (1ull << p);
            if (lane == 0) g_kept[n*NPOST + cnt] = ch*64 + p;
            cnt++;
            if (cnt == NPOST) break;
            unsigned long long rw = __shfl_sync(FULL, (p<32) ? m0 : m1, p & 31);
            W |= rw;
        }
        if (cnt >= NPOST) break;

        unsigned long long kb = keptb;
        while (kb) {
            int p = __ffsll((long long)kb) - 1;
            kb &= kb - 1;
            size_t row = (size_t)(ch*64 + p)*MASKW;
            r0 |= mk[row + lane];
            r1 |= mk[row + 32 + lane];
            if (64 + lane < MASKW) r2 |= mk[row + 64 + lane];
        }
    }
    if (lane == 0) g_keptcnt[n] = cnt;
}

// ---------------------------------------------------------------------------
// Final outputs: rois, roi_indices, vmask
// ---------------------------------------------------------------------------
__global__ void out_kernel(float* __restrict__ out) {
    int t = blockIdx.x*256 + threadIdx.x;
    if (t >= NB*NPOST) return;
    int n = t/NPOST, r = t%NPOST;
    int cnt = g_keptcnt[n];
    float4 b = make_float4(0.f,0.f,0.f,0.f);
    float vm = 0.f;
    if (r < cnt) {
        b = g_boxes[n*NPRE + g_kept[n*NPOST + r]];
        vm = 1.f;
    }
    out[OFF_ROIS + (size_t)t*4 + 0] = b.x;
    out[OFF_ROIS + (size_t)t*4 + 1] = b.y;
    out[OFF_ROIS + (size_t)t*4 + 2] = b.z;
    out[OFF_ROIS + (size_t)t*4 + 3] = b.w;
    out[OFF_RIDX + t]  = (float)n;
    out[OFF_VMASK + t] = vm;
}

// ---------------------------------------------------------------------------
// Launch
// ---------------------------------------------------------------------------
extern "C" void kernel_launch(void* const* d_in, const int* in_sizes, int n_in,
                              void* d_out, int out_size) {
    const float* x  = (const float*)d_in[0];
    const float* w  = (const float*)d_in[1];
    const float* b  = (const float*)d_in[2];
    const float* sw = (const float*)d_in[3];
    const float* sb = (const float*)d_in[4];
    const float* lw = (const float*)d_in[5];
    const float* lb = (const float*)d_in[6];
    float* out = (float*)d_out;

    wt_kernel<<<(CIN*CIN*9 + 255)/256, 256>>>(w);
    conv_kernel<<<dim3(8,64,2), 256>>>(x, b);
    heads_kernel<<<dim3(64,2), 256>>>(sw, sb, lw, lb, d_in[7], d_in[8], out);

    void* tmp;
    float *ks, *ko;
    int *vi, *vo;
    cudaGetSymbolAddress(&tmp, g_cub_temp);
    cudaGetSymbolAddress((void**)&ks, g_score);
    cudaGetSymbolAddress((void**)&ko, g_keys_out);
    cudaGetSymbolAddress((void**)&vi, g_idx_in);
    cudaGetSymbolAddress((void**)&vo, g_idx_out);

    for (int n=0; n<NB; n++) {
        size_t tb = 0;
        cub::DeviceRadixSort::SortPairsDescending(nullptr, tb,
            ks + n*ATOT, ko + n*ATOT, vi, vo + n*ATOT, ATOT, 0, 32, (cudaStream_t)0);
        if (tb <= sizeof(g_cub_temp)) {
            cub::DeviceRadixSort::SortPairsDescending(tmp, tb,
                ks + n*ATOT, ko + n*ATOT, vi, vo + n*ATOT, ATOT, 0, 32, (cudaStream_t)0);
        }
    }

    gather_kernel<<<(NB*NPRE + 255)/256, 256>>>();
    mask_kernel<<<dim3(MASKW, MASKW, NB), 64>>>();
    scan_kernel<<<NB, 32>>>();
    out_kernel<<<(NB*NPOST + 255)/256, 256>>>(out);
}

// round 6
// speedup vs baseline: 1.8457x; 1.8457x over previous
#include <cuda_runtime.h>
#include <cuda_bf16.h>
#include <cuda_fp16.h>
#include <math_constants.h>
#include <cub/cub.cuh>
#include <cstdint>

// ---------------------------------------------------------------------------
// Problem constants
// ---------------------------------------------------------------------------
#define HH 64
#define WWID 64
#define CIN 512
#define NB 2
#define NANCH 9
#define ATOT (HH*WWID*NANCH)      // 36864
#define NPRE 6000
#define NPOST 300
#define MASKW 94                  // ceil(6000/64)
#define NMS_T 0.7f

#define MTOT (NB*HH*WWID)         // 8192 pixel rows
#define KTAP 9

// Output layout (float32, concatenated in reference return order)
#define OFF_LOCS   0
#define OFF_SCORES (NB*ATOT*4)
#define OFF_ROIS   (OFF_SCORES + NB*ATOT*2)
#define OFF_RIDX   (OFF_ROIS + NB*NPOST*4)
#define OFF_ANCHOR (OFF_RIDX + NB*NPOST)
#define OFF_VMASK  (OFF_ANCHOR + ATOT*4)

#define APLSZ ((size_t)MTOT*CIN)        // elements per A fp16 plane
#define BPLSZ ((size_t)KTAP*CIN*CIN)    // elements per B fp16 plane
#define BSCALE 64.0f
#define BUNSCALE 0.015625f

// ---------------------------------------------------------------------------
// Scratch
// ---------------------------------------------------------------------------
__device__ float g_h[(size_t)MTOT*CIN];          // conv output NHWC [m][c]
__device__ __half g_axh[2*APLSZ];                // input fp16 planes (NHWC)
__device__ __half g_bxh[2*BPLSZ];                // weight planes [tap][k][c], x64
__device__ float g_score[NB*ATOT];
__device__ float g_keys_out[NB*ATOT];
__device__ int   g_idx_in[ATOT];
__device__ int   g_idx_out[NB*ATOT];
__device__ float4 g_roi[NB*ATOT];
__device__ float4 g_boxes[NB*NPRE];
__device__ float g_boxsc[NB*NPRE];
__device__ unsigned long long g_mask[(size_t)NB*NPRE*MASKW];
__device__ int g_kept[NB*NPOST];
__device__ int g_keptcnt[NB];
__device__ __align__(256) unsigned char g_cub_temp[8<<20];

// ---------------------------------------------------------------------------
// PTX helpers
// ---------------------------------------------------------------------------
__device__ __forceinline__ uint32_t smem_u32(const void* p) {
    uint32_t a;
    asm("{ .reg .u64 t; cvta.to.shared.u64 t, %1; cvt.u32.u64 %0, t; }" : "=r"(a) : "l"(p));
    return a;
}
__device__ __forceinline__ void cp16(uint32_t dst, const void* src, int srcsize) {
    asm volatile("cp.async.cg.shared.global [%0], [%1], 16, %2;"
                 :: "r"(dst), "l"(src), "r"(srcsize) : "memory");
}
__device__ __forceinline__ void cp_commit() { asm volatile("cp.async.commit_group;" ::: "memory"); }
template<int N> __device__ __forceinline__ void cp_wait() {
    asm volatile("cp.async.wait_group %0;" :: "n"(N) : "memory");
}
__device__ __forceinline__ uint32_t lds_u32(uint32_t a) {
    uint32_t v; asm volatile("ld.shared.b32 %0, [%1];" : "=r"(v) : "r"(a)); return v;
}

// fp16 2-way split: v ≈ h0 + h1 (22-bit coverage for normal-range values)
__device__ __forceinline__ void f16split(float v, __half& o0, __half& o1) {
    __half h0 = __float2half_rn(v);
    float r = v - __half2float(h0);
    o0 = h0;
    o1 = __float2half_rn(r);
}

// mma.sync m16n8k16 fp16 -> fp32, C = D (accumulate)
#define MMA_F16(d, a, b) \
    asm volatile("mma.sync.aligned.m16n8k16.row.col.f32.f16.f16.f32 " \
                 "{%0,%1,%2,%3},{%4,%5,%6,%7},{%8,%9},{%0,%1,%2,%3};" \
                 : "+f"((d)[0]), "+f"((d)[1]), "+f"((d)[2]), "+f"((d)[3]) \
                 : "r"((a)[0]), "r"((a)[1]), "r"((a)[2]), "r"((a)[3]), \
                   "r"((b)[0]), "r"((b)[1]))

// mma.sync with C = 0 (starts a fresh accumulation window)
#define MMA_F16_ZC(d, a, b, z) \
    asm volatile("mma.sync.aligned.m16n8k16.row.col.f32.f16.f16.f32 " \
                 "{%0,%1,%2,%3},{%4,%5,%6,%7},{%8,%9},{%10,%10,%10,%10};" \
                 : "=f"((d)[0]), "=f"((d)[1]), "=f"((d)[2]), "=f"((d)[3]) \
                 : "r"((a)[0]), "r"((a)[1]), "r"((a)[2]), "r"((a)[3]), \
                   "r"((b)[0]), "r"((b)[1]), "f"(z))

// ---------------------------------------------------------------------------
// Split/transpose input: NCHW -> NHWC fp16 x2
// ---------------------------------------------------------------------------
__global__ void split_x_kernel(const float* __restrict__ x) {
    __shared__ float tile[32][33];
    int pt = blockIdx.x, ct = blockIdx.y, n = blockIdx.z;
    int tx = threadIdx.x, ty = threadIdx.y;
#pragma unroll
    for (int r = 0; r < 4; r++) {
        int c = ct*32 + ty + r*8;
        int p = pt*32 + tx;
        tile[ty + r*8][tx] = x[((size_t)(n*CIN + c))*4096 + p];
    }
    __syncthreads();
#pragma unroll
    for (int r = 0; r < 4; r++) {
        int p = pt*32 + ty + r*8;
        int c = ct*32 + tx;
        float v = tile[tx][ty + r*8];
        __half h0, h1;
        f16split(v, h0, h1);
        size_t o = ((size_t)(n*4096 + p))*CIN + c;
        g_axh[o] = h0;
        g_axh[APLSZ + o] = h1;
    }
}

// Weights: w[k][c][tap] -> planes [tap][k][c] fp16 x2, scaled by 64
__global__ void split_w_kernel(const float* __restrict__ w) {
    int e = blockIdx.x*256 + threadIdx.x;
    if (e >= KTAP*CIN*CIN) return;
    int c = e & 511;
    int k = (e >> 9) & 511;
    int tap = e >> 18;
    float v = w[((size_t)k*CIN + c)*KTAP + tap] * BSCALE;
    __half h0, h1;
    f16split(v, h0, h1);
    g_bxh[e] = h0;
    g_bxh[BPLSZ + e] = h1;
}

// ---------------------------------------------------------------------------
// fp16x3 emulated-fp32 conv GEMM with windowed accumulation.
// Block tile M=128 x N=128; grid (64, 4) = 256 CTAs. 256 threads, 8 warps:
// wm = warp&3 (4 m-subtiles of 32), wn = warp>>2 (2 n-subtiles of 64).
// Warp tile 32x64: mt in {0,1} (m16 tiles), nt 0..7 (n8 tiles).
// K window = one chunk (32 cin): MMA acc zeroed per chunk (C=0 on first mma),
// drained into fp32 running sum -> kills HMMA alignment-truncation bias.
// Smem rows: 32 fp16 (64B) + 16B pad = 80B stride (bank-conflict-free frags).
// Stage: A 2x10240 + B 2x10240 = 40960 B; double buffered.
// ---------------------------------------------------------------------------
#define A_PL 10240
#define B_OFF 20480
#define B_PL 10240
#define STAGE_BYTES 40960
#define SMEM_DYN (2*STAGE_BYTES)
#define NSTAGE 144                // 9 taps x 16 cin-chunks of 32

__device__ __forceinline__ void load_chunk(int chunk, uint32_t base,
                                           int n, int y0, int k0, int tid) {
    int tap = chunk >> 4;
    int c0  = (chunk & 15) * 32;
    int dy = tap/3 - 1, dx = tap%3 - 1;
    // A: 2 planes x 128 rows x 4 segs of 16B = 1024 cp16
#pragma unroll
    for (int r = 0; r < 4; r++) {
        int i = r*256 + tid;
        int plane = i >> 9;
        int rs = i & 511;
        int row = rs >> 2, seg = rs & 3;
        int y = y0 + (row >> 6) + dy;
        int x = (row & 63) + dx;
        bool valid = ((unsigned)y < 64u) && ((unsigned)x < 64u);
        const __half* src = valid ?
            g_axh + (size_t)plane*APLSZ + ((size_t)(n*4096 + y*64 + x))*CIN + c0 + seg*8
            : g_axh;
        uint32_t dst = base + plane*A_PL + row*80 + seg*16;
        cp16(dst, src, valid ? 16 : 0);
    }
    // B: 2 planes x 128 rows x 4 segs = 1024 cp16
#pragma unroll
    for (int r = 0; r < 4; r++) {
        int i = r*256 + tid;
        int plane = i >> 9;
        int rs = i & 511;
        int row = rs >> 2, seg = rs & 3;
        const __half* src = g_bxh + (size_t)plane*BPLSZ +
            ((size_t)tap*CIN + k0 + row)*CIN + c0 + seg*8;
        uint32_t dst = base + B_OFF + plane*B_PL + row*80 + seg*16;
        cp16(dst, src, 16);
    }
    cp_commit();
}

__global__ void __launch_bounds__(256) mma_conv_kernel(const float* __restrict__ bias) {
    extern __shared__ char smem[];
    uint32_t sb = smem_u32(smem);
    int tid = threadIdx.x;
    int lane = tid & 31, w = tid >> 5;
    int wm = w & 3, wn = w >> 2;
    int g = lane >> 2, t = lane & 3;

    int p0 = blockIdx.x * 128;
    int n  = p0 >> 12;
    int y0 = (p0 & 4095) >> 6;
    int k0 = blockIdx.y * 128;

    float run[2][8][4];
    float acc[2][8][4];
#pragma unroll
    for (int mt=0; mt<2; mt++)
#pragma unroll
        for (int nt=0; nt<8; nt++)
#pragma unroll
            for (int j=0; j<4; j++) run[mt][nt][j] = 0.f;

    float fz = 0.0f;

    load_chunk(0, sb, n, y0, k0, tid);

    for (int i = 0; i < NSTAGE; i++) {
        if (i + 1 < NSTAGE) {
            load_chunk(i+1, sb + ((i+1)&1)*STAGE_BYTES, n, y0, k0, tid);
            cp_wait<1>();
        } else {
            cp_wait<0>();
        }
        __syncthreads();

        uint32_t st = sb + (i&1)*STAGE_BYTES;
        uint32_t aRowH = st + (wm*32 + g)*80;
        uint32_t aRowL = aRowH + A_PL;
        uint32_t bRowH = st + B_OFF + (wn*64 + g)*80;
        uint32_t bRowL = bRowH + B_PL;

#pragma unroll
        for (int ks = 0; ks < 2; ks++) {
            uint32_t off0 = (uint32_t)(ks*32 + 4*t);
            uint32_t off1 = off0 + 16;
            uint32_t ah[2][4], al[2][4], bh[8][2], bl[8][2];
#pragma unroll
            for (int mt = 0; mt < 2; mt++) {
                uint32_t ra = aRowH + mt*1280;
                ah[mt][0] = lds_u32(ra + off0);
                ah[mt][1] = lds_u32(ra + 640 + off0);
                ah[mt][2] = lds_u32(ra + off1);
                ah[mt][3] = lds_u32(ra + 640 + off1);
                uint32_t rl = aRowL + mt*1280;
                al[mt][0] = lds_u32(rl + off0);
                al[mt][1] = lds_u32(rl + 640 + off0);
                al[mt][2] = lds_u32(rl + off1);
                al[mt][3] = lds_u32(rl + 640 + off1);
            }
#pragma unroll
            for (int nt = 0; nt < 8; nt++) {
                uint32_t rb = bRowH + nt*640;
                bh[nt][0] = lds_u32(rb + off0);
                bh[nt][1] = lds_u32(rb + off1);
                uint32_t rb2 = bRowL + nt*640;
                bl[nt][0] = lds_u32(rb2 + off0);
                bl[nt][1] = lds_u32(rb2 + off1);
            }
#pragma unroll
            for (int mt = 0; mt < 2; mt++)
#pragma unroll
                for (int nt = 0; nt < 8; nt++) {
                    if (ks == 0) {
                        MMA_F16_ZC(acc[mt][nt], ah[mt], bh[nt], fz);
                    } else {
                        MMA_F16(acc[mt][nt], ah[mt], bh[nt]);
                    }
                    MMA_F16(acc[mt][nt], ah[mt], bl[nt]);
                    MMA_F16(acc[mt][nt], al[mt], bh[nt]);
                }
        }
        // Drain window into running fp32 sum (RN adds, small acc magnitude)
#pragma unroll
        for (int mt = 0; mt < 2; mt++)
#pragma unroll
            for (int nt = 0; nt < 8; nt++)
#pragma unroll
                for (int j = 0; j < 4; j++)
                    run[mt][nt][j] += acc[mt][nt][j];
        __syncthreads();
    }

    // Epilogue: unscale, bias + relu, store NHWC
#pragma unroll
    for (int mt = 0; mt < 2; mt++) {
        int m0 = p0 + wm*32 + mt*16 + g;
#pragma unroll
        for (int nt = 0; nt < 8; nt++) {
            int ch = k0 + wn*64 + nt*8 + t*2;
            float b0 = bias[ch], b1 = bias[ch+1];
            float2 v0, v1;
            v0.x = fmaxf(fmaf(run[mt][nt][0], BUNSCALE, b0), 0.f);
            v0.y = fmaxf(fmaf(run[mt][nt][1], BUNSCALE, b1), 0.f);
            v1.x = fmaxf(fmaf(run[mt][nt][2], BUNSCALE, b0), 0.f);
            v1.y = fmaxf(fmaf(run[mt][nt][3], BUNSCALE, b1), 0.f);
            *(float2*)&g_h[(size_t)m0*CIN + ch] = v0;
            *(float2*)&g_h[(size_t)(m0+8)*CIN + ch] = v1;
        }
    }
}

// ---------------------------------------------------------------------------
// Anchor (matches numpy _anchor_base + integer shift)
// ---------------------------------------------------------------------------
__device__ __forceinline__ void anchor_calc(int y, int x, int k,
                                            float& o0, float& o1, float& o2, float& o3) {
    const double ratios[3] = {0.5, 1.0, 2.0};
    const double scales[3] = {8.0, 16.0, 32.0};
    int i = k/3, j = k%3;
    double h = 16.0*scales[j]*sqrt(ratios[i]);
    double w = 16.0*scales[j]*sqrt(1.0/ratios[i]);
    float b0 = (float)(8.0 - h*0.5);
    float b1 = (float)(8.0 - w*0.5);
    float b2 = (float)(8.0 + h*0.5);
    float b3 = (float)(8.0 + w*0.5);
    o0 = (float)((double)b0 + (double)(y*16));
    o1 = (float)((double)b1 + (double)(x*16));
    o2 = (float)((double)b2 + (double)(y*16));
    o3 = (float)((double)b3 + (double)(x*16));
}

__device__ __forceinline__ float load_dim(const void* p) {
    int iv = *(const int*)p;
    if (iv > 0 && iv < (1<<20)) return (float)iv;
    return *(const float*)p;
}

// ---------------------------------------------------------------------------
// Heads (reads NHWC h): 1x1 score+loc conv, softmax, anchors, decode.
// ---------------------------------------------------------------------------
__global__ __launch_bounds__(256) void heads_kernel(const float* __restrict__ sw,
                                                    const float* __restrict__ sb,
                                                    const float* __restrict__ lw,
                                                    const float* __restrict__ lb,
                                                    const void* ihp, const void* iwp,
                                                    float* __restrict__ out) {
    __shared__ float s_h[32][65];
    __shared__ float s_w2[54][32];
    __shared__ float s_o[54][64];

    int y = blockIdx.x, n = blockIdx.y;
    int tid = threadIdx.x;
    int px = tid & 63, og = tid >> 6;

    float acc[14];
#pragma unroll
    for (int t=0;t<14;t++) acc[t]=0.f;

    for (int c0=0; c0<CIN; c0+=32) {
        for (int e=tid; e<2048; e+=256) {
            int p = e>>5, cc = e&31;
            s_h[cc][p] = g_h[((size_t)(n*4096 + y*64 + p))*CIN + c0 + cc];
        }
        for (int e=tid; e<1728; e+=256) {
            int o = e>>5, cc = e&31;
            s_w2[o][cc] = (o<18) ? sw[o*CIN + c0+cc] : lw[(o-18)*CIN + c0+cc];
        }
        __syncthreads();
#pragma unroll 8
        for (int cc=0; cc<32; cc++) {
            float hv = s_h[cc][px];
#pragma unroll
            for (int t=0; t<14; t++) {
                int o = og + 4*t;
                if (o < 54) acc[t] = fmaf(s_w2[o][cc], hv, acc[t]);
            }
        }
        __syncthreads();
    }

    int pix = y*64 + px;
#pragma unroll
    for (int t=0; t<14; t++) {
        int o = og + 4*t;
        if (o < 54) {
            float v = acc[t] + ((o<18) ? sb[o] : lb[o-18]);
            s_o[o][px] = v;
            if (o < 18)
                out[OFF_SCORES + ((size_t)n*ATOT + (size_t)pix*9 + (o>>1))*2 + (o&1)] = v;
            else {
                int c = o-18;
                out[OFF_LOCS + ((size_t)n*ATOT + (size_t)pix*9 + (c>>2))*4 + (c&3)] = v;
            }
        }
    }
    __syncthreads();

    float img_h = load_dim(ihp), img_w = load_dim(iwp);

    for (int e=tid; e<576; e+=256) {
        int p2 = e & 63;
        int k  = e >> 6;
        float s0 = s_o[2*k][p2], s1 = s_o[2*k+1][p2];
        float m  = fmaxf(s0,s1);
        float e0 = expf(s0-m), e1 = expf(s1-m);
        float fg = e1/(e0+e1);

        float d0 = s_o[18+4*k+0][p2];
        float d1 = s_o[18+4*k+1][p2];
        float d2 = s_o[18+4*k+2][p2];
        float d3 = s_o[18+4*k+3][p2];

        float a0,a1,a2,a3;
        anchor_calc(y, p2, k, a0,a1,a2,a3);

        float ah = a2-a0, aw = a3-a1;
        float acy = a0 + 0.5f*ah, acx = a1 + 0.5f*aw;
        float cy = fmaf(d0, ah, acy);
        float cx = fmaf(d1, aw, acx);
        float h  = expf(d2)*ah;
        float w  = expf(d3)*aw;
        float r0 = fminf(fmaxf(cy-0.5f*h, 0.f), img_h);
        float r1 = fminf(fmaxf(cx-0.5f*w, 0.f), img_w);
        float r2 = fminf(fmaxf(cy+0.5f*h, 0.f), img_h);
        float r3 = fminf(fmaxf(cx+0.5f*w, 0.f), img_w);
        bool valid = (r2-r0 >= 16.f) && (r3-r1 >= 16.f);

        int aidx = (y*64 + p2)*9 + k;
        g_score[n*ATOT + aidx] = valid ? fg : -CUDART_INF_F;
        g_roi[(size_t)n*ATOT + aidx] = make_float4(r0,r1,r2,r3);
        g_idx_in[aidx] = aidx;
        if (n == 0) {
            out[OFF_ANCHOR + (size_t)aidx*4 + 0] = a0;
            out[OFF_ANCHOR + (size_t)aidx*4 + 1] = a1;
            out[OFF_ANCHOR + (size_t)aidx*4 + 2] = a2;
            out[OFF_ANCHOR + (size_t)aidx*4 + 3] = a3;
        }
    }
}

// ---------------------------------------------------------------------------
// Gather top-6000 boxes + scores after sort
// ---------------------------------------------------------------------------
__global__ void gather_kernel() {
    int t = blockIdx.x*256 + threadIdx.x;
    if (t >= NB*NPRE) return;
    int n = t/NPRE, i = t%NPRE;
    int idx = g_idx_out[n*ATOT + i];
    g_boxes[t] = g_roi[(size_t)n*ATOT + idx];
    g_boxsc[t] = g_keys_out[n*ATOT + i];
}

// ---------------------------------------------------------------------------
// NMS bitmask
// ---------------------------------------------------------------------------
__global__ __launch_bounds__(64) void mask_kernel() {
    int n  = blockIdx.z;
    int jb = blockIdx.x;
    int ib = blockIdx.y;
    int t  = threadIdx.x;

    __shared__ float4 cb[64];
    int j = jb*64 + t;
    cb[t] = (j < NPRE) ? g_boxes[n*NPRE + j] : make_float4(0.f,0.f,0.f,0.f);
    __syncthreads();

    int i = ib*64 + t;
    if (i >= NPRE) return;
    float4 bi = g_boxes[n*NPRE + i];
    float areai = (bi.z-bi.x)*(bi.w-bi.y);

    unsigned long long word = 0ull;
    int jmax = min(64, NPRE - jb*64);
    for (int jj=0; jj<jmax; jj++) {
        float4 bj = cb[jj];
        float areaj = (bj.z-bj.x)*(bj.w-bj.y);
        float ih = fmaxf(fminf(bi.z,bj.z) - fmaxf(bi.x,bj.x), 0.f);
        float iw = fmaxf(fminf(bi.w,bj.w) - fmaxf(bi.y,bj.y), 0.f);
        float inter = ih*iw;
        float iou = inter/(areai + areaj - inter + 1e-9f);
        if (iou > NMS_T) word |= (1ull << jj);
    }
    g_mask[((size_t)n*NPRE + i)*MASKW + jb] = word;
}

// ---------------------------------------------------------------------------
// Greedy NMS scan: one warp per batch
// ---------------------------------------------------------------------------
__global__ void scan_kernel() {
    int n = blockIdx.x;
    int lane = threadIdx.x;
    const unsigned FULL = 0xffffffffu;

    unsigned long long r0=0ull, r1=0ull, r2=0ull;
    int cnt = 0;
    const unsigned long long* mk = g_mask + (size_t)n*NPRE*MASKW;
    const float* sc = g_boxsc + n*NPRE;

    for (int ch=0; ch<MASKW; ch++) {
        int i0 = ch*64 + lane, i1 = i0 + 32;
        unsigned long long m0 = (i0 < NPRE) ? mk[(size_t)i0*MASKW + ch] : 0ull;
        unsigned long long m1 = (i1 < NPRE) ? mk[(size_t)i1*MASKW + ch] : 0ull;
        float s0 = (i0 < NPRE) ? sc[i0] : -CUDART_INF_F;
        float s1 = (i1 < NPRE) ? sc[i1] : -CUDART_INF_F;
        unsigned inv0 = __ballot_sync(FULL, !isfinite(s0));
        unsigned inv1 = __ballot_sync(FULL, !isfinite(s1));
        unsigned long long W = (unsigned long long)inv0 | ((unsigned long long)inv1 << 32);

        int seg = ch >> 5, ln = ch & 31;
        unsigned long long rr = (seg==0) ? r0 : ((seg==1) ? r1 : r2);
        W |= __shfl_sync(FULL, rr, ln);

        unsigned long long keptb = 0ull;
        while (~W) {
            int p = __ffsll((long long)(~W)) - 1;
            keptb |= (1ull << p);
            if (lane == 0) g_kept[n*NPOST + cnt] = ch*64 + p;
            cnt++;
            if (cnt == NPOST) break;
            unsigned long long rw = __shfl_sync(FULL, (p<32) ? m0 : m1, p & 31);
            W |= rw;
        }
        if (cnt >= NPOST) break;

        unsigned long long kb = keptb;
        while (kb) {
            int p = __ffsll((long long)kb) - 1;
            kb &= kb - 1;
            size_t row = (size_t)(ch*64 + p)*MASKW;
            r0 |= mk[row + lane];
            r1 |= mk[row + 32 + lane];
            if (64 + lane < MASKW) r2 |= mk[row + 64 + lane];
        }
    }
    if (lane == 0) g_keptcnt[n] = cnt;
}

// ---------------------------------------------------------------------------
// Final outputs
// ---------------------------------------------------------------------------
__global__ void out_kernel(float* __restrict__ out) {
    int t = blockIdx.x*256 + threadIdx.x;
    if (t >= NB*NPOST) return;
    int n = t/NPOST, r = t%NPOST;
    int cnt = g_keptcnt[n];
    float4 b = make_float4(0.f,0.f,0.f,0.f);
    float vm = 0.f;
    if (r < cnt) {
        b = g_boxes[n*NPRE + g_kept[n*NPOST + r]];
        vm = 1.f;
    }
    out[OFF_ROIS + (size_t)t*4 + 0] = b.x;
    out[OFF_ROIS + (size_t)t*4 + 1] = b.y;
    out[OFF_ROIS + (size_t)t*4 + 2] = b.z;
    out[OFF_ROIS + (size_t)t*4 + 3] = b.w;
    out[OFF_RIDX + t]  = (float)n;
    out[OFF_VMASK + t] = vm;
}

// ---------------------------------------------------------------------------
// Launch
// ---------------------------------------------------------------------------
extern "C" void kernel_launch(void* const* d_in, const int* in_sizes, int n_in,
                              void* d_out, int out_size) {
    const float* x  = (const float*)d_in[0];
    const float* w  = (const float*)d_in[1];
    const float* b  = (const float*)d_in[2];
    const float* sw = (const float*)d_in[3];
    const float* sb = (const float*)d_in[4];
    const float* lw = (const float*)d_in[5];
    const float* lb = (const float*)d_in[6];
    float* out = (float*)d_out;

    cudaFuncSetAttribute(mma_conv_kernel,
                         cudaFuncAttributeMaxDynamicSharedMemorySize, SMEM_DYN);

    split_x_kernel<<<dim3(128, 16, 2), dim3(32, 8)>>>(x);
    split_w_kernel<<<(KTAP*CIN*CIN + 255)/256, 256>>>(w);
    mma_conv_kernel<<<dim3(64, 4), 256, SMEM_DYN>>>(b);
    heads_kernel<<<dim3(64, 2), 256>>>(sw, sb, lw, lb, d_in[7], d_in[8], out);

    void* tmp;
    float *ks, *ko;
    int *vi, *vo;
    cudaGetSymbolAddress(&tmp, g_cub_temp);
    cudaGetSymbolAddress((void**)&ks, g_score);
    cudaGetSymbolAddress((void**)&ko, g_keys_out);
    cudaGetSymbolAddress((void**)&vi, g_idx_in);
    cudaGetSymbolAddress((void**)&vo, g_idx_out);

    for (int n=0; n<NB; n++) {
        size_t tb = 0;
        cub::DeviceRadixSort::SortPairsDescending(nullptr, tb,
            ks + n*ATOT, ko + n*ATOT, vi, vo + n*ATOT, ATOT, 0, 32, (cudaStream_t)0);
        if (tb <= sizeof(g_cub_temp)) {
            cub::DeviceRadixSort::SortPairsDescending(tmp, tb,
                ks + n*ATOT, ko + n*ATOT, vi, vo + n*ATOT, ATOT, 0, 32, (cudaStream_t)0);
        }
    }

    gather_kernel<<<(NB*NPRE + 255)/256, 256>>>();
    mask_kernel<<<dim3(MASKW, MASKW, NB), 64>>>();
    scan_kernel<<<NB, 32>>>();
    out_kernel<<<(NB*NPOST + 255)/256, 256>>>(out);
}

// round 7
// speedup vs baseline: 1.9665x; 1.0655x over previous
#include <cuda_runtime.h>
#include <cuda_bf16.h>
#include <cuda_fp16.h>
#include <math_constants.h>
#include <cub/cub.cuh>
#include <cstdint>

// ---------------------------------------------------------------------------
// Problem constants
// ---------------------------------------------------------------------------
#define HH 64
#define WWID 64
#define CIN 512
#define NB 2
#define NANCH 9
#define ATOT (HH*WWID*NANCH)      // 36864
#define NPRE 6000
#define NPOST 300
#define MASKW 94                  // ceil(6000/64)
#define NMS_T 0.7f

#define MTOT (NB*HH*WWID)         // 8192 pixel rows
#define KTAP 9

// Output layout (float32, concatenated in reference return order)
#define OFF_LOCS   0
#define OFF_SCORES (NB*ATOT*4)
#define OFF_ROIS   (OFF_SCORES + NB*ATOT*2)
#define OFF_RIDX   (OFF_ROIS + NB*NPOST*4)
#define OFF_ANCHOR (OFF_RIDX + NB*NPOST)
#define OFF_VMASK  (OFF_ANCHOR + ATOT*4)

#define APLSZ ((size_t)MTOT*CIN)        // elements per A fp16 plane
#define BPLSZ ((size_t)KTAP*CIN*CIN)    // elements per B fp16 plane
#define BSCALE 64.0f
#define BUNSCALE 0.015625f

// ---------------------------------------------------------------------------
// Scratch
// ---------------------------------------------------------------------------
__device__ float g_h[(size_t)MTOT*CIN];          // conv output NHWC [m][c]
__device__ __half g_axh[2*APLSZ];                // input fp16 planes (NHWC)
__device__ __half g_bxh[2*BPLSZ];                // weight planes [tap][k][c], x64
__device__ float g_part[(size_t)4*NB*56*4096];  // heads partials [q][n][o][pix]
__device__ float g_score[NB*ATOT];
__device__ unsigned long long g_key64[NB*ATOT];
__device__ unsigned long long g_key64_out[NB*ATOT];
__device__ int   g_val[NB*ATOT];
__device__ int   g_val_out[NB*ATOT];
__device__ float4 g_roi[NB*ATOT];
__device__ float4 g_boxes[NB*NPRE];
__device__ float g_boxsc[NB*NPRE];
__device__ unsigned long long g_mask[(size_t)NB*NPRE*MASKW];
__device__ int g_kept[NB*NPOST];
__device__ int g_keptcnt[NB];
__device__ __align__(256) unsigned char g_cub_temp[8<<20];

// ---------------------------------------------------------------------------
// PTX helpers
// ---------------------------------------------------------------------------
__device__ __forceinline__ uint32_t smem_u32(const void* p) {
    uint32_t a;
    asm("{ .reg .u64 t; cvta.to.shared.u64 t, %1; cvt.u32.u64 %0, t; }" : "=r"(a) : "l"(p));
    return a;
}
__device__ __forceinline__ void cp16(uint32_t dst, const void* src, int srcsize) {
    asm volatile("cp.async.cg.shared.global [%0], [%1], 16, %2;"
                 :: "r"(dst), "l"(src), "r"(srcsize) : "memory");
}
__device__ __forceinline__ void cp_commit() { asm volatile("cp.async.commit_group;" ::: "memory"); }
template<int N> __device__ __forceinline__ void cp_wait() {
    asm volatile("cp.async.wait_group %0;" :: "n"(N) : "memory");
}
__device__ __forceinline__ uint32_t lds_u32(uint32_t a) {
    uint32_t v; asm volatile("ld.shared.b32 %0, [%1];" : "=r"(v) : "r"(a)); return v;
}

// fp16 2-way split
__device__ __forceinline__ void f16split(float v, __half& o0, __half& o1) {
    __half h0 = __float2half_rn(v);
    float r = v - __half2float(h0);
    o0 = h0;
    o1 = __float2half_rn(r);
}

#define MMA_F16(d, a, b) \
    asm volatile("mma.sync.aligned.m16n8k16.row.col.f32.f16.f16.f32 " \
                 "{%0,%1,%2,%3},{%4,%5,%6,%7},{%8,%9},{%0,%1,%2,%3};" \
                 : "+f"((d)[0]), "+f"((d)[1]), "+f"((d)[2]), "+f"((d)[3]) \
                 : "r"((a)[0]), "r"((a)[1]), "r"((a)[2]), "r"((a)[3]), \
                   "r"((b)[0]), "r"((b)[1]))

#define MMA_F16_ZC(d, a, b, z) \
    asm volatile("mma.sync.aligned.m16n8k16.row.col.f32.f16.f16.f32 " \
                 "{%0,%1,%2,%3},{%4,%5,%6,%7},{%8,%9},{%10,%10,%10,%10};" \
                 : "=f"((d)[0]), "=f"((d)[1]), "=f"((d)[2]), "=f"((d)[3]) \
                 : "r"((a)[0]), "r"((a)[1]), "r"((a)[2]), "r"((a)[3]), \
                   "r"((b)[0]), "r"((b)[1]), "f"(z))

// ---------------------------------------------------------------------------
// Split/transpose input: NCHW -> NHWC fp16 x2
// ---------------------------------------------------------------------------
__global__ void split_x_kernel(const float* __restrict__ x) {
    __shared__ float tile[32][33];
    int pt = blockIdx.x, ct = blockIdx.y, n = blockIdx.z;
    int tx = threadIdx.x, ty = threadIdx.y;
#pragma unroll
    for (int r = 0; r < 4; r++) {
        int c = ct*32 + ty + r*8;
        int p = pt*32 + tx;
        tile[ty + r*8][tx] = x[((size_t)(n*CIN + c))*4096 + p];
    }
    __syncthreads();
#pragma unroll
    for (int r = 0; r < 4; r++) {
        int p = pt*32 + ty + r*8;
        int c = ct*32 + tx;
        float v = tile[tx][ty + r*8];
        __half h0, h1;
        f16split(v, h0, h1);
        size_t o = ((size_t)(n*4096 + p))*CIN + c;
        g_axh[o] = h0;
        g_axh[APLSZ + o] = h1;
    }
}

// Weights: w[k][c][tap] -> planes [tap][k][c] fp16 x2, scaled by 64
__global__ void split_w_kernel(const float* __restrict__ w) {
    int e = blockIdx.x*256 + threadIdx.x;
    if (e >= KTAP*CIN*CIN) return;
    int c = e & 511;
    int k = (e >> 9) & 511;
    int tap = e >> 18;
    float v = w[((size_t)k*CIN + c)*KTAP + tap] * BSCALE;
    __half h0, h1;
    f16split(v, h0, h1);
    g_bxh[e] = h0;
    g_bxh[BPLSZ + e] = h1;
}

// ---------------------------------------------------------------------------
// fp16x3 emulated-fp32 conv GEMM, windowed accumulation, 3-stage cp.async.
// Block tile M=128 x N=128; grid (64, 4) = 256 CTAs. 256 threads, 8 warps.
// ---------------------------------------------------------------------------
#define A_PL 10240
#define B_OFF 20480
#define B_PL 10240
#define STAGE_BYTES 40960
#define SMEM_DYN (3*STAGE_BYTES)
#define NSTAGE 144

__device__ __forceinline__ void load_chunk(int chunk, uint32_t base,
                                           int n, int y0, int k0, int tid) {
    int tap = chunk >> 4;
    int c0  = (chunk & 15) * 32;
    int dy = tap/3 - 1, dx = tap%3 - 1;
#pragma unroll
    for (int r = 0; r < 4; r++) {
        int i = r*256 + tid;
        int plane = i >> 9;
        int rs = i & 511;
        int row = rs >> 2, seg = rs & 3;
        int y = y0 + (row >> 6) + dy;
        int x = (row & 63) + dx;
        bool valid = ((unsigned)y < 64u) && ((unsigned)x < 64u);
        const __half* src = valid ?
            g_axh + (size_t)plane*APLSZ + ((size_t)(n*4096 + y*64 + x))*CIN + c0 + seg*8
            : g_axh;
        uint32_t dst = base + plane*A_PL + row*80 + seg*16;
        cp16(dst, src, valid ? 16 : 0);
    }
#pragma unroll
    for (int r = 0; r < 4; r++) {
        int i = r*256 + tid;
        int plane = i >> 9;
        int rs = i & 511;
        int row = rs >> 2, seg = rs & 3;
        const __half* src = g_bxh + (size_t)plane*BPLSZ +
            ((size_t)tap*CIN + k0 + row)*CIN + c0 + seg*8;
        uint32_t dst = base + B_OFF + plane*B_PL + row*80 + seg*16;
        cp16(dst, src, 16);
    }
    cp_commit();
}

__global__ void __launch_bounds__(256) mma_conv_kernel(const float* __restrict__ bias) {
    extern __shared__ char smem[];
    uint32_t sb = smem_u32(smem);
    int tid = threadIdx.x;
    int lane = tid & 31, w = tid >> 5;
    int wm = w & 3, wn = w >> 2;
    int g = lane >> 2, t = lane & 3;

    int p0 = blockIdx.x * 128;
    int n  = p0 >> 12;
    int y0 = (p0 & 4095) >> 6;
    int k0 = blockIdx.y * 128;

    float run[2][8][4];
    float acc[2][8][4];
#pragma unroll
    for (int mt=0; mt<2; mt++)
#pragma unroll
        for (int nt=0; nt<8; nt++)
#pragma unroll
            for (int j=0; j<4; j++) run[mt][nt][j] = 0.f;

    float fz = 0.0f;

    load_chunk(0, sb, n, y0, k0, tid);
    load_chunk(1, sb + STAGE_BYTES, n, y0, k0, tid);

    for (int i = 0; i < NSTAGE; i++) {
        if (i + 2 < NSTAGE) {
            load_chunk(i+2, sb + ((i+2)%3)*STAGE_BYTES, n, y0, k0, tid);
            cp_wait<2>();
        } else if (i + 1 < NSTAGE) {
            cp_wait<1>();
        } else {
            cp_wait<0>();
        }
        __syncthreads();

        uint32_t st = sb + (i%3)*STAGE_BYTES;
        uint32_t aRowH = st + (wm*32 + g)*80;
        uint32_t aRowL = aRowH + A_PL;
        uint32_t bRowH = st + B_OFF + (wn*64 + g)*80;
        uint32_t bRowL = bRowH + B_PL;

#pragma unroll
        for (int ks = 0; ks < 2; ks++) {
            uint32_t off0 = (uint32_t)(ks*32 + 4*t);
            uint32_t off1 = off0 + 16;
            uint32_t ah[2][4], al[2][4], bh[8][2], bl[8][2];
#pragma unroll
            for (int mt = 0; mt < 2; mt++) {
                uint32_t ra = aRowH + mt*1280;
                ah[mt][0] = lds_u32(ra + off0);
                ah[mt][1] = lds_u32(ra + 640 + off0);
                ah[mt][2] = lds_u32(ra + off1);
                ah[mt][3] = lds_u32(ra + 640 + off1);
                uint32_t rl = aRowL + mt*1280;
                al[mt][0] = lds_u32(rl + off0);
                al[mt][1] = lds_u32(rl + 640 + off0);
                al[mt][2] = lds_u32(rl + off1);
                al[mt][3] = lds_u32(rl + 640 + off1);
            }
#pragma unroll
            for (int nt = 0; nt < 8; nt++) {
                uint32_t rb = bRowH + nt*640;
                bh[nt][0] = lds_u32(rb + off0);
                bh[nt][1] = lds_u32(rb + off1);
                uint32_t rb2 = bRowL + nt*640;
                bl[nt][0] = lds_u32(rb2 + off0);
                bl[nt][1] = lds_u32(rb2 + off1);
            }
#pragma unroll
            for (int mt = 0; mt < 2; mt++)
#pragma unroll
                for (int nt = 0; nt < 8; nt++) {
                    if (ks == 0) {
                        MMA_F16_ZC(acc[mt][nt], ah[mt], bh[nt], fz);
                    } else {
                        MMA_F16(acc[mt][nt], ah[mt], bh[nt]);
                    }
                    MMA_F16(acc[mt][nt], ah[mt], bl[nt]);
                    MMA_F16(acc[mt][nt], al[mt], bh[nt]);
                }
        }
#pragma unroll
        for (int mt = 0; mt < 2; mt++)
#pragma unroll
            for (int nt = 0; nt < 8; nt++)
#pragma unroll
                for (int j = 0; j < 4; j++)
                    run[mt][nt][j] += acc[mt][nt][j];
        __syncthreads();
    }

#pragma unroll
    for (int mt = 0; mt < 2; mt++) {
        int m0 = p0 + wm*32 + mt*16 + g;
#pragma unroll
        for (int nt = 0; nt < 8; nt++) {
            int ch = k0 + wn*64 + nt*8 + t*2;
            float b0 = bias[ch], b1 = bias[ch+1];
            float2 v0, v1;
            v0.x = fmaxf(fmaf(run[mt][nt][0], BUNSCALE, b0), 0.f);
            v0.y = fmaxf(fmaf(run[mt][nt][1], BUNSCALE, b1), 0.f);
            v1.x = fmaxf(fmaf(run[mt][nt][2], BUNSCALE, b0), 0.f);
            v1.y = fmaxf(fmaf(run[mt][nt][3], BUNSCALE, b1), 0.f);
            *(float2*)&g_h[(size_t)m0*CIN + ch] = v0;
            *(float2*)&g_h[(size_t)(m0+8)*CIN + ch] = v1;
        }
    }
}

// ---------------------------------------------------------------------------
// Anchor (matches numpy _anchor_base + integer shift)
// ---------------------------------------------------------------------------
__device__ __forceinline__ void anchor_calc(int y, int x, int k,
                                            float& o0, float& o1, float& o2, float& o3) {
    const double ratios[3] = {0.5, 1.0, 2.0};
    const double scales[3] = {8.0, 16.0, 32.0};
    int i = k/3, j = k%3;
    double h = 16.0*scales[j]*sqrt(ratios[i]);
    double w = 16.0*scales[j]*sqrt(1.0/ratios[i]);
    float b0 = (float)(8.0 - h*0.5);
    float b1 = (float)(8.0 - w*0.5);
    float b2 = (float)(8.0 + h*0.5);
    float b3 = (float)(8.0 + w*0.5);
    o0 = (float)((double)b0 + (double)(y*16));
    o1 = (float)((double)b1 + (double)(x*16));
    o2 = (float)((double)b2 + (double)(y*16));
    o3 = (float)((double)b3 + (double)(x*16));
}

__device__ __forceinline__ float load_dim(const void* p) {
    int iv = *(const int*)p;
    if (iv > 0 && iv < (1<<20)) return (float)iv;
    return *(const float*)p;
}

// ---------------------------------------------------------------------------
// Heads partial: 1x1 conv over a 128-channel quarter. grid (64, 2, 4).
// Writes partials to g_part[((q*2+n)*56+o)*4096 + pix] (no bias).
// ---------------------------------------------------------------------------
__global__ __launch_bounds__(256) void heads_part_kernel(const float* __restrict__ sw,
                                                         const float* __restrict__ lw) {
    __shared__ float s_h[32][65];
    __shared__ float s_w2[54][33];

    int y = blockIdx.x, n = blockIdx.y, q = blockIdx.z;
    int tid = threadIdx.x;
    int px = tid & 63, og = tid >> 6;

    float acc[14];
#pragma unroll
    for (int t=0;t<14;t++) acc[t]=0.f;

    int cbase = q*128;
    for (int c0=cbase; c0<cbase+128; c0+=32) {
        for (int e=tid; e<2048; e+=256) {
            int p = e>>5, cc = e&31;
            s_h[cc][p] = g_h[((size_t)(n*4096 + y*64 + p))*CIN + c0 + cc];
        }
        for (int e=tid; e<1728; e+=256) {
            int o = e>>5, cc = e&31;
            s_w2[o][cc] = (o<18) ? sw[o*CIN + c0+cc] : lw[(o-18)*CIN + c0+cc];
        }
        __syncthreads();
#pragma unroll 8
        for (int cc=0; cc<32; cc++) {
            float hv = s_h[cc][px];
#pragma unroll
            for (int t=0; t<14; t++) {
                int o = og + 4*t;
                if (o < 54) acc[t] = fmaf(s_w2[o][cc], hv, acc[t]);
            }
        }
        __syncthreads();
    }

    int pix = y*64 + px;
#pragma unroll
    for (int t=0; t<14; t++) {
        int o = og + 4*t;
        if (o < 54)
            g_part[((size_t)((q*2+n)*56 + o))*4096 + pix] = acc[t];
    }
}

// ---------------------------------------------------------------------------
// Finalize: sum quarters (deterministic order) + bias, write locs/scores,
// softmax, anchors, decode, build sort keys. grid (64, 2).
// ---------------------------------------------------------------------------
__global__ __launch_bounds__(256) void finalize_kernel(const float* __restrict__ sb,
                                                       const float* __restrict__ lb,
                                                       const void* ihp, const void* iwp,
                                                       float* __restrict__ out) {
    __shared__ float s_o[54][64];
    int y = blockIdx.x, n = blockIdx.y;
    int tid = threadIdx.x;

    for (int e=tid; e<3456; e+=256) {
        int px = e & 63, o = e >> 6;
        size_t base = (size_t)y*64 + px;
        float s = g_part[((size_t)((0*2+n)*56 + o))*4096 + base];
        s += g_part[((size_t)((1*2+n)*56 + o))*4096 + base];
        s += g_part[((size_t)((2*2+n)*56 + o))*4096 + base];
        s += g_part[((size_t)((3*2+n)*56 + o))*4096 + base];
        s += (o<18) ? sb[o] : lb[o-18];
        s_o[o][px] = s;
        int pix = y*64 + px;
        if (o < 18)
            out[OFF_SCORES + ((size_t)n*ATOT + (size_t)pix*9 + (o>>1))*2 + (o&1)] = s;
        else {
            int c = o-18;
            out[OFF_LOCS + ((size_t)n*ATOT + (size_t)pix*9 + (c>>2))*4 + (c&3)] = s;
        }
    }
    __syncthreads();

    float img_h = load_dim(ihp), img_w = load_dim(iwp);

    for (int e=tid; e<576; e+=256) {
        int p2 = e & 63;
        int k  = e >> 6;
        float s0 = s_o[2*k][p2], s1 = s_o[2*k+1][p2];
        float m  = fmaxf(s0,s1);
        float e0 = expf(s0-m), e1 = expf(s1-m);
        float fg = e1/(e0+e1);

        float d0 = s_o[18+4*k+0][p2];
        float d1 = s_o[18+4*k+1][p2];
        float d2 = s_o[18+4*k+2][p2];
        float d3 = s_o[18+4*k+3][p2];

        float a0,a1,a2,a3;
        anchor_calc(y, p2, k, a0,a1,a2,a3);

        float ah = a2-a0, aw = a3-a1;
        float acy = a0 + 0.5f*ah, acx = a1 + 0.5f*aw;
        float cy = fmaf(d0, ah, acy);
        float cx = fmaf(d1, aw, acx);
        float h  = expf(d2)*ah;
        float w  = expf(d3)*aw;
        float r0 = fminf(fmaxf(cy-0.5f*h, 0.f), img_h);
        float r1 = fminf(fmaxf(cx-0.5f*w, 0.f), img_w);
        float r2 = fminf(fmaxf(cy+0.5f*h, 0.f), img_h);
        float r3 = fminf(fmaxf(cx+0.5f*w, 0.f), img_w);
        bool valid = (r2-r0 >= 16.f) && (r3-r1 >= 16.f);

        int aidx = (y*64 + p2)*9 + k;
        int gi = n*ATOT + aidx;
        float sc = valid ? fg : -CUDART_INF_F;
        g_score[gi] = sc;
        g_roi[gi] = make_float4(r0,r1,r2,r3);
        // sort key: batch bit (batch 0 first under descending) | flipped float
        uint32_t bts = __float_as_uint(sc);
        uint32_t u = (bts & 0x80000000u) ? ~bts : (bts | 0x80000000u);
        g_key64[gi] = ((unsigned long long)(1 - n) << 32) | u;
        g_val[gi] = gi;
        if (n == 0) {
            out[OFF_ANCHOR + (size_t)aidx*4 + 0] = a0;
            out[OFF_ANCHOR + (size_t)aidx*4 + 1] = a1;
            out[OFF_ANCHOR + (size_t)aidx*4 + 2] = a2;
            out[OFF_ANCHOR + (size_t)aidx*4 + 3] = a3;
        }
    }
}

// ---------------------------------------------------------------------------
// Gather top-6000 boxes + scores after sort
// ---------------------------------------------------------------------------
__global__ void gather_kernel() {
    int t = blockIdx.x*256 + threadIdx.x;
    if (t >= NB*NPRE) return;
    int n = t/NPRE, i = t%NPRE;
    int gi = g_val_out[n*ATOT + i];
    g_boxes[t] = g_roi[gi];
    g_boxsc[t] = g_score[gi];
}

// ---------------------------------------------------------------------------
// NMS bitmask
// ---------------------------------------------------------------------------
__global__ __launch_bounds__(64) void mask_kernel() {
    int n  = blockIdx.z;
    int jb = blockIdx.x;
    int ib = blockIdx.y;
    int t  = threadIdx.x;

    __shared__ float4 cb[64];
    int j = jb*64 + t;
    cb[t] = (j < NPRE) ? g_boxes[n*NPRE + j] : make_float4(0.f,0.f,0.f,0.f);
    __syncthreads();

    int i = ib*64 + t;
    if (i >= NPRE) return;
    float4 bi = g_boxes[n*NPRE + i];
    float areai = (bi.z-bi.x)*(bi.w-bi.y);

    unsigned long long word = 0ull;
    int jmax = min(64, NPRE - jb*64);
    for (int jj=0; jj<jmax; jj++) {
        float4 bj = cb[jj];
        float areaj = (bj.z-bj.x)*(bj.w-bj.y);
        float ih = fmaxf(fminf(bi.z,bj.z) - fmaxf(bi.x,bj.x), 0.f);
        float iw = fmaxf(fminf(bi.w,bj.w) - fmaxf(bi.y,bj.y), 0.f);
        float inter = ih*iw;
        float iou = inter/(areai + areaj - inter + 1e-9f);
        if (iou > NMS_T) word |= (1ull << jj);
    }
    g_mask[((size_t)n*NPRE + i)*MASKW + jb] = word;
}

// ---------------------------------------------------------------------------
// Greedy NMS scan: one warp per batch
// ---------------------------------------------------------------------------
__global__ void scan_kernel() {
    int n = blockIdx.x;
    int lane = threadIdx.x;
    const unsigned FULL = 0xffffffffu;

    unsigned long long r0=0ull, r1=0ull, r2=0ull;
    int cnt = 0;
    const unsigned long long* mk = g_mask + (size_t)n*NPRE*MASKW;
    const float* sc = g_boxsc + n*NPRE;

    for (int ch=0; ch<MASKW; ch++) {
        int i0 = ch*64 + lane, i1 = i0 + 32;
        unsigned long long m0 = (i0 < NPRE) ? mk[(size_t)i0*MASKW + ch] : 0ull;
        unsigned long long m1 = (i1 < NPRE) ? mk[(size_t)i1*MASKW + ch] : 0ull;
        float s0 = (i0 < NPRE) ? sc[i0] : -CUDART_INF_F;
        float s1 = (i1 < NPRE) ? sc[i1] : -CUDART_INF_F;
        unsigned inv0 = __ballot_sync(FULL, !isfinite(s0));
        unsigned inv1 = __ballot_sync(FULL, !isfinite(s1));
        unsigned long long W = (unsigned long long)inv0 | ((unsigned long long)inv1 << 32);

        int seg = ch >> 5, ln = ch & 31;
        unsigned long long rr = (seg==0) ? r0 : ((seg==1) ? r1 : r2);
        W |= __shfl_sync(FULL, rr, ln);

        unsigned long long keptb = 0ull;
        while (~W) {
            int p = __ffsll((long long)(~W)) - 1;
            keptb |= (1ull << p);
            if (lane == 0) g_kept[n*NPOST + cnt] = ch*64 + p;
            cnt++;
            if (cnt == NPOST) break;
            unsigned long long rw = __shfl_sync(FULL, (p<32) ? m0 : m1, p & 31);
            W |= rw;
        }
        if (cnt >= NPOST) break;

        unsigned long long kb = keptb;
        while (kb) {
            int p = __ffsll((long long)kb) - 1;
            kb &= kb - 1;
            size_t row = (size_t)(ch*64 + p)*MASKW;
            r0 |= mk[row + lane];
            r1 |= mk[row + 32 + lane];
            if (64 + lane < MASKW) r2 |= mk[row + 64 + lane];
        }
    }
    if (lane == 0) g_keptcnt[n] = cnt;
}

// ---------------------------------------------------------------------------
// Final outputs
// ---------------------------------------------------------------------------
__global__ void out_kernel(float* __restrict__ out) {
    int t = blockIdx.x*256 + threadIdx.x;
    if (t >= NB*NPOST) return;
    int n = t/NPOST, r = t%NPOST;
    int cnt = g_keptcnt[n];
    float4 b = make_float4(0.f,0.f,0.f,0.f);
    float vm = 0.f;
    if (r < cnt) {
        b = g_boxes[n*NPRE + g_kept[n*NPOST + r]];
        vm = 1.f;
    }
    out[OFF_ROIS + (size_t)t*4 + 0] = b.x;
    out[OFF_ROIS + (size_t)t*4 + 1] = b.y;
    out[OFF_ROIS + (size_t)t*4 + 2] = b.z;
    out[OFF_ROIS + (size_t)t*4 + 3] = b.w;
    out[OFF_RIDX + t]  = (float)n;
    out[OFF_VMASK + t] = vm;
}

// ---------------------------------------------------------------------------
// Launch
// ---------------------------------------------------------------------------
extern "C" void kernel_launch(void* const* d_in, const int* in_sizes, int n_in,
                              void* d_out, int out_size) {
    const float* x  = (const float*)d_in[0];
    const float* w  = (const float*)d_in[1];
    const float* b  = (const float*)d_in[2];
    const float* sw = (const float*)d_in[3];
    const float* sb = (const float*)d_in[4];
    const float* lw = (const float*)d_in[5];
    const float* lb = (const float*)d_in[6];
    float* out = (float*)d_out;

    cudaFuncSetAttribute(mma_conv_kernel,
                         cudaFuncAttributeMaxDynamicSharedMemorySize, SMEM_DYN);

    split_x_kernel<<<dim3(128, 16, 2), dim3(32, 8)>>>(x);
    split_w_kernel<<<(KTAP*CIN*CIN + 255)/256, 256>>>(w);
    mma_conv_kernel<<<dim3(64, 4), 256, SMEM_DYN>>>(b);
    heads_part_kernel<<<dim3(64, 2, 4), 256>>>(sw, lw);
    finalize_kernel<<<dim3(64, 2), 256>>>(sb, lb, d_in[7], d_in[8], out);

    void* tmp;
    unsigned long long *ki, *ko;
    int *vi, *vo;
    cudaGetSymbolAddress(&tmp, g_cub_temp);
    cudaGetSymbolAddress((void**)&ki, g_key64);
    cudaGetSymbolAddress((void**)&ko, g_key64_out);
    cudaGetSymbolAddress((void**)&vi, g_val);
    cudaGetSymbolAddress((void**)&vo, g_val_out);

    {
        size_t tb = 0;
        cub::DeviceRadixSort::SortPairsDescending(nullptr, tb,
            ki, ko, vi, vo, NB*ATOT, 0, 33, (cudaStream_t)0);
        if (tb <= sizeof(g_cub_temp)) {
            cub::DeviceRadixSort::SortPairsDescending(tmp, tb,
                ki, ko, vi, vo, NB*ATOT, 0, 33, (cudaStream_t)0);
        }
    }

    gather_kernel<<<(NB*NPRE + 255)/256, 256>>>();
    mask_kernel<<<dim3(MASKW, MASKW, NB), 64>>>();
    scan_kernel<<<NB, 32>>>();
    out_kernel<<<(NB*NPOST + 255)/256, 256>>>(out);
}

// round 8
// speedup vs baseline: 2.1240x; 1.0801x over previous
#include <cuda_runtime.h>
#include <cuda_bf16.h>
#include <cuda_fp16.h>
#include <math_constants.h>
#include <cub/cub.cuh>
#include <cstdint>

// ---------------------------------------------------------------------------
// Problem constants
// ---------------------------------------------------------------------------
#define HH 64
#define WWID 64
#define CIN 512
#define NB 2
#define NANCH 9
#define ATOT (HH*WWID*NANCH)      // 36864
#define NPRE 6000
#define NPOST 300
#define MASKW 94                  // ceil(6000/64)
#define NMS_T 0.7f

#define MTOT (NB*HH*WWID)         // 8192 pixel rows
#define KTAP 9

// Output layout (float32, concatenated in reference return order)
#define OFF_LOCS   0
#define OFF_SCORES (NB*ATOT*4)
#define OFF_ROIS   (OFF_SCORES + NB*ATOT*2)
#define OFF_RIDX   (OFF_ROIS + NB*NPOST*4)
#define OFF_ANCHOR (OFF_RIDX + NB*NPOST)
#define OFF_VMASK  (OFF_ANCHOR + ATOT*4)

#define APLSZ ((size_t)MTOT*CIN)        // elements per A fp16 plane
#define BPLSZ ((size_t)KTAP*CIN*CIN)    // elements per B fp16 plane
#define BSCALE 64.0f
#define BUNSCALE 0.015625f
#define NQ 8                             // heads channel-split factor

// ---------------------------------------------------------------------------
// Scratch
// ---------------------------------------------------------------------------
__device__ float g_h[(size_t)MTOT*CIN];          // conv output NHWC [m][c]
__device__ __half g_axh[2*APLSZ];                // input fp16 planes (NHWC)
__device__ __half g_bxh[2*BPLSZ];                // weight planes [tap][k][c], x64
__device__ float g_part[(size_t)NQ*NB*56*4096]; // heads partials [q][n][o][pix]
__device__ float g_score[NB*ATOT];
__device__ uint32_t g_key32[NB*ATOT];
__device__ uint32_t g_key32_out[NB*ATOT];
__device__ int   g_val[NB*ATOT];
__device__ int   g_val_out[NB*ATOT];
__device__ float4 g_roi[NB*ATOT];
__device__ float4 g_boxes[NB*NPRE];
__device__ float g_boxsc[NB*NPRE];
__device__ unsigned long long g_mask[(size_t)NB*NPRE*MASKW];
__device__ int g_kept[NB*NPOST];
__device__ int g_keptcnt[NB];
__device__ __align__(256) unsigned char g_cub_temp[8<<20];

// ---------------------------------------------------------------------------
// PTX helpers
// ---------------------------------------------------------------------------
__device__ __forceinline__ uint32_t smem_u32(const void* p) {
    uint32_t a;
    asm("{ .reg .u64 t; cvta.to.shared.u64 t, %1; cvt.u32.u64 %0, t; }" : "=r"(a) : "l"(p));
    return a;
}
__device__ __forceinline__ void cp16(uint32_t dst, const void* src, int srcsize) {
    asm volatile("cp.async.cg.shared.global [%0], [%1], 16, %2;"
                 :: "r"(dst), "l"(src), "r"(srcsize) : "memory");
}
__device__ __forceinline__ void cp_commit() { asm volatile("cp.async.commit_group;" ::: "memory"); }
template<int N> __device__ __forceinline__ void cp_wait() {
    asm volatile("cp.async.wait_group %0;" :: "n"(N) : "memory");
}

#define LDSM4(r0, r1, r2, r3, a) \
    asm volatile("ldmatrix.sync.aligned.m8n8.x4.shared.b16 {%0,%1,%2,%3}, [%4];" \
                 : "=r"(r0), "=r"(r1), "=r"(r2), "=r"(r3) : "r"(a))

// fp16 2-way split
__device__ __forceinline__ void f16split(float v, __half& o0, __half& o1) {
    __half h0 = __float2half_rn(v);
    float r = v - __half2float(h0);
    o0 = h0;
    o1 = __float2half_rn(r);
}

#define MMA_F16(d, a, b) \
    asm volatile("mma.sync.aligned.m16n8k16.row.col.f32.f16.f16.f32 " \
                 "{%0,%1,%2,%3},{%4,%5,%6,%7},{%8,%9},{%0,%1,%2,%3};" \
                 : "+f"((d)[0]), "+f"((d)[1]), "+f"((d)[2]), "+f"((d)[3]) \
                 : "r"((a)[0]), "r"((a)[1]), "r"((a)[2]), "r"((a)[3]), \
                   "r"((b)[0]), "r"((b)[1]))

#define MMA_F16_ZC(d, a, b, z) \
    asm volatile("mma.sync.aligned.m16n8k16.row.col.f32.f16.f16.f32 " \
                 "{%0,%1,%2,%3},{%4,%5,%6,%7},{%8,%9},{%10,%10,%10,%10};" \
                 : "=f"((d)[0]), "=f"((d)[1]), "=f"((d)[2]), "=f"((d)[3]) \
                 : "r"((a)[0]), "r"((a)[1]), "r"((a)[2]), "r"((a)[3]), \
                   "r"((b)[0]), "r"((b)[1]), "f"(z))

// ---------------------------------------------------------------------------
// Split/transpose input: NCHW -> NHWC fp16 x2
// ---------------------------------------------------------------------------
__global__ void split_x_kernel(const float* __restrict__ x) {
    __shared__ float tile[32][33];
    int pt = blockIdx.x, ct = blockIdx.y, n = blockIdx.z;
    int tx = threadIdx.x, ty = threadIdx.y;
#pragma unroll
    for (int r = 0; r < 4; r++) {
        int c = ct*32 + ty + r*8;
        int p = pt*32 + tx;
        tile[ty + r*8][tx] = x[((size_t)(n*CIN + c))*4096 + p];
    }
    __syncthreads();
#pragma unroll
    for (int r = 0; r < 4; r++) {
        int p = pt*32 + ty + r*8;
        int c = ct*32 + tx;
        float v = tile[tx][ty + r*8];
        __half h0, h1;
        f16split(v, h0, h1);
        size_t o = ((size_t)(n*4096 + p))*CIN + c;
        g_axh[o] = h0;
        g_axh[APLSZ + o] = h1;
    }
}

// Weights: w[k][c][tap] -> planes [tap][k][c] fp16 x2, scaled by 64
__global__ void split_w_kernel(const float* __restrict__ w) {
    int e = blockIdx.x*256 + threadIdx.x;
    if (e >= KTAP*CIN*CIN) return;
    int c = e & 511;
    int k = (e >> 9) & 511;
    int tap = e >> 18;
    float v = w[((size_t)k*CIN + c)*KTAP + tap] * BSCALE;
    __half h0, h1;
    f16split(v, h0, h1);
    g_bxh[e] = h0;
    g_bxh[BPLSZ + e] = h1;
}

// ---------------------------------------------------------------------------
// fp16x3 emulated-fp32 conv GEMM, windowed accumulation, 3-stage cp.async,
// ldmatrix fragment loads.
// ---------------------------------------------------------------------------
#define A_PL 10240
#define B_OFF 20480
#define B_PL 10240
#define STAGE_BYTES 40960
#define SMEM_DYN (3*STAGE_BYTES)
#define NSTAGE 144

__device__ __forceinline__ void load_chunk(int chunk, uint32_t base,
                                           int n, int y0, int k0, int tid) {
    int tap = chunk >> 4;
    int c0  = (chunk & 15) * 32;
    int dy = tap/3 - 1, dx = tap%3 - 1;
#pragma unroll
    for (int r = 0; r < 4; r++) {
        int i = r*256 + tid;
        int plane = i >> 9;
        int rs = i & 511;
        int row = rs >> 2, seg = rs & 3;
        int y = y0 + (row >> 6) + dy;
        int x = (row & 63) + dx;
        bool valid = ((unsigned)y < 64u) && ((unsigned)x < 64u);
        const __half* src = valid ?
            g_axh + (size_t)plane*APLSZ + ((size_t)(n*4096 + y*64 + x))*CIN + c0 + seg*8
            : g_axh;
        uint32_t dst = base + plane*A_PL + row*80 + seg*16;
        cp16(dst, src, valid ? 16 : 0);
    }
#pragma unroll
    for (int r = 0; r < 4; r++) {
        int i = r*256 + tid;
        int plane = i >> 9;
        int rs = i & 511;
        int row = rs >> 2, seg = rs & 3;
        const __half* src = g_bxh + (size_t)plane*BPLSZ +
            ((size_t)tap*CIN + k0 + row)*CIN + c0 + seg*8;
        uint32_t dst = base + B_OFF + plane*B_PL + row*80 + seg*16;
        cp16(dst, src, 16);
    }
    cp_commit();
}

__global__ void __launch_bounds__(256) mma_conv_kernel(const float* __restrict__ bias) {
    extern __shared__ char smem[];
    uint32_t sb = smem_u32(smem);
    int tid = threadIdx.x;
    int lane = tid & 31, w = tid >> 5;
    int wm = w & 3, wn = w >> 2;
    int g = lane >> 2, t = lane & 3;

    int p0 = blockIdx.x * 128;
    int n  = p0 >> 12;
    int y0 = (p0 & 4095) >> 6;
    int k0 = blockIdx.y * 128;

    // ldmatrix per-lane address offsets (mat m = lane>>3, row r = lane&7)
    // A x4 mats: [rows lo,klo][rows hi,klo][rows lo,khi][rows hi,khi]
    uint32_t aoff = (uint32_t)((wm*32 + ((lane>>3)&1)*8 + (lane&7))*80 + (lane>>4)*16);
    // B x4 mats: [nt,klo][nt,khi][nt+1,klo][nt+1,khi]
    uint32_t boff = (uint32_t)(B_OFF + (wn*64 + (lane>>4)*8 + (lane&7))*80 + ((lane>>3)&1)*16);

    float run[2][8][4];
    float acc[2][8][4];
#pragma unroll
    for (int mt=0; mt<2; mt++)
#pragma unroll
        for (int nt=0; nt<8; nt++)
#pragma unroll
            for (int j=0; j<4; j++) run[mt][nt][j] = 0.f;

    float fz = 0.0f;

    load_chunk(0, sb, n, y0, k0, tid);
    load_chunk(1, sb + STAGE_BYTES, n, y0, k0, tid);

    for (int i = 0; i < NSTAGE; i++) {
        if (i + 2 < NSTAGE) {
            load_chunk(i+2, sb + ((i+2)%3)*STAGE_BYTES, n, y0, k0, tid);
            cp_wait<2>();
        } else if (i + 1 < NSTAGE) {
            cp_wait<1>();
        } else {
            cp_wait<0>();
        }
        __syncthreads();

        uint32_t st = sb + (i%3)*STAGE_BYTES;

#pragma unroll
        for (int ks = 0; ks < 2; ks++) {
            uint32_t kof = (uint32_t)(ks*32);
            uint32_t aH = st + aoff + kof;
            uint32_t aL = aH + A_PL;
            uint32_t bH = st + boff + kof;
            uint32_t bL = bH + B_PL;

            uint32_t ah[2][4], al[2][4], bh[8][2], bl[8][2];
            LDSM4(ah[0][0], ah[0][1], ah[0][2], ah[0][3], aH);
            LDSM4(ah[1][0], ah[1][1], ah[1][2], ah[1][3], aH + 1280);
            LDSM4(al[0][0], al[0][1], al[0][2], al[0][3], aL);
            LDSM4(al[1][0], al[1][1], al[1][2], al[1][3], aL + 1280);
            LDSM4(bh[0][0], bh[0][1], bh[1][0], bh[1][1], bH);
            LDSM4(bh[2][0], bh[2][1], bh[3][0], bh[3][1], bH + 1280);
            LDSM4(bh[4][0], bh[4][1], bh[5][0], bh[5][1], bH + 2560);
            LDSM4(bh[6][0], bh[6][1], bh[7][0], bh[7][1], bH + 3840);
            LDSM4(bl[0][0], bl[0][1], bl[1][0], bl[1][1], bL);
            LDSM4(bl[2][0], bl[2][1], bl[3][0], bl[3][1], bL + 1280);
            LDSM4(bl[4][0], bl[4][1], bl[5][0], bl[5][1], bL + 2560);
            LDSM4(bl[6][0], bl[6][1], bl[7][0], bl[7][1], bL + 3840);

#pragma unroll
            for (int mt = 0; mt < 2; mt++)
#pragma unroll
                for (int nt = 0; nt < 8; nt++) {
                    if (ks == 0) {
                        MMA_F16_ZC(acc[mt][nt], ah[mt], bh[nt], fz);
                    } else {
                        MMA_F16(acc[mt][nt], ah[mt], bh[nt]);
                    }
                    MMA_F16(acc[mt][nt], ah[mt], bl[nt]);
                    MMA_F16(acc[mt][nt], al[mt], bh[nt]);
                }
        }
#pragma unroll
        for (int mt = 0; mt < 2; mt++)
#pragma unroll
            for (int nt = 0; nt < 8; nt++)
#pragma unroll
                for (int j = 0; j < 4; j++)
                    run[mt][nt][j] += acc[mt][nt][j];
        __syncthreads();
    }

#pragma unroll
    for (int mt = 0; mt < 2; mt++) {
        int m0 = p0 + wm*32 + mt*16 + g;
#pragma unroll
        for (int nt = 0; nt < 8; nt++) {
            int ch = k0 + wn*64 + nt*8 + t*2;
            float b0 = bias[ch], b1 = bias[ch+1];
            float2 v0, v1;
            v0.x = fmaxf(fmaf(run[mt][nt][0], BUNSCALE, b0), 0.f);
            v0.y = fmaxf(fmaf(run[mt][nt][1], BUNSCALE, b1), 0.f);
            v1.x = fmaxf(fmaf(run[mt][nt][2], BUNSCALE, b0), 0.f);
            v1.y = fmaxf(fmaf(run[mt][nt][3], BUNSCALE, b1), 0.f);
            *(float2*)&g_h[(size_t)m0*CIN + ch] = v0;
            *(float2*)&g_h[(size_t)(m0+8)*CIN + ch] = v1;
        }
    }
}

// ---------------------------------------------------------------------------
// Anchor (matches numpy _anchor_base + integer shift)
// ---------------------------------------------------------------------------
__device__ __forceinline__ void anchor_calc(int y, int x, int k,
                                            float& o0, float& o1, float& o2, float& o3) {
    const double ratios[3] = {0.5, 1.0, 2.0};
    const double scales[3] = {8.0, 16.0, 32.0};
    int i = k/3, j = k%3;
    double h = 16.0*scales[j]*sqrt(ratios[i]);
    double w = 16.0*scales[j]*sqrt(1.0/ratios[i]);
    float b0 = (float)(8.0 - h*0.5);
    float b1 = (float)(8.0 - w*0.5);
    float b2 = (float)(8.0 + h*0.5);
    float b3 = (float)(8.0 + w*0.5);
    o0 = (float)((double)b0 + (double)(y*16));
    o1 = (float)((double)b1 + (double)(x*16));
    o2 = (float)((double)b2 + (double)(y*16));
    o3 = (float)((double)b3 + (double)(x*16));
}

__device__ __forceinline__ float load_dim(const void* p) {
    int iv = *(const int*)p;
    if (iv > 0 && iv < (1<<20)) return (float)iv;
    return *(const float*)p;
}

// ---------------------------------------------------------------------------
// Heads partial: 1x1 conv over a 64-channel slice. grid (64, 2, 8).
// ---------------------------------------------------------------------------
__global__ __launch_bounds__(256) void heads_part_kernel(const float* __restrict__ sw,
                                                         const float* __restrict__ lw) {
    __shared__ float s_h[32][65];
    __shared__ float s_w2[54][33];

    int y = blockIdx.x, n = blockIdx.y, q = blockIdx.z;
    int tid = threadIdx.x;
    int px = tid & 63, og = tid >> 6;

    float acc[14];
#pragma unroll
    for (int t=0;t<14;t++) acc[t]=0.f;

    int cbase = q*64;
    for (int c0=cbase; c0<cbase+64; c0+=32) {
        for (int e=tid; e<2048; e+=256) {
            int p = e>>5, cc = e&31;
            s_h[cc][p] = g_h[((size_t)(n*4096 + y*64 + p))*CIN + c0 + cc];
        }
        for (int e=tid; e<1728; e+=256) {
            int o = e>>5, cc = e&31;
            s_w2[o][cc] = (o<18) ? sw[o*CIN + c0+cc] : lw[(o-18)*CIN + c0+cc];
        }
        __syncthreads();
#pragma unroll 8
        for (int cc=0; cc<32; cc++) {
            float hv = s_h[cc][px];
#pragma unroll
            for (int t=0; t<14; t++) {
                int o = og + 4*t;
                if (o < 54) acc[t] = fmaf(s_w2[o][cc], hv, acc[t]);
            }
        }
        __syncthreads();
    }

    int pix = y*64 + px;
#pragma unroll
    for (int t=0; t<14; t++) {
        int o = og + 4*t;
        if (o < 54)
            g_part[((size_t)((q*2+n)*56 + o))*4096 + pix] = acc[t];
    }
}

// ---------------------------------------------------------------------------
// Finalize: deterministic 8-way partial sum + bias, outputs, softmax, decode,
// 32-bit sort keys. grid (64, 2).
// ---------------------------------------------------------------------------
__global__ __launch_bounds__(256) void finalize_kernel(const float* __restrict__ sb,
                                                       const float* __restrict__ lb,
                                                       const void* ihp, const void* iwp,
                                                       float* __restrict__ out) {
    __shared__ float s_o[54][64];
    int y = blockIdx.x, n = blockIdx.y;
    int tid = threadIdx.x;

    for (int e=tid; e<3456; e+=256) {
        int px = e & 63, o = e >> 6;
        size_t base = (size_t)y*64 + px;
        float s = 0.f;
#pragma unroll
        for (int q = 0; q < NQ; q++)
            s += g_part[((size_t)((q*2+n)*56 + o))*4096 + base];
        s += (o<18) ? sb[o] : lb[o-18];
        s_o[o][px] = s;
        int pix = y*64 + px;
        if (o < 18)
            out[OFF_SCORES + ((size_t)n*ATOT + (size_t)pix*9 + (o>>1))*2 + (o&1)] = s;
        else {
            int c = o-18;
            out[OFF_LOCS + ((size_t)n*ATOT + (size_t)pix*9 + (c>>2))*4 + (c&3)] = s;
        }
    }
    __syncthreads();

    float img_h = load_dim(ihp), img_w = load_dim(iwp);

    for (int e=tid; e<576; e+=256) {
        int p2 = e & 63;
        int k  = e >> 6;
        float s0 = s_o[2*k][p2], s1 = s_o[2*k+1][p2];
        float m  = fmaxf(s0,s1);
        float e0 = expf(s0-m), e1 = expf(s1-m);
        float fg = e1/(e0+e1);

        float d0 = s_o[18+4*k+0][p2];
        float d1 = s_o[18+4*k+1][p2];
        float d2 = s_o[18+4*k+2][p2];
        float d3 = s_o[18+4*k+3][p2];

        float a0,a1,a2,a3;
        anchor_calc(y, p2, k, a0,a1,a2,a3);

        float ah = a2-a0, aw = a3-a1;
        float acy = a0 + 0.5f*ah, acx = a1 + 0.5f*aw;
        float cy = fmaf(d0, ah, acy);
        float cx = fmaf(d1, aw, acx);
        float h  = expf(d2)*ah;
        float w  = expf(d3)*aw;
        float r0 = fminf(fmaxf(cy-0.5f*h, 0.f), img_h);
        float r1 = fminf(fmaxf(cx-0.5f*w, 0.f), img_w);
        float r2 = fminf(fmaxf(cy+0.5f*h, 0.f), img_h);
        float r3 = fminf(fmaxf(cx+0.5f*w, 0.f), img_w);
        bool valid = (r2-r0 >= 16.f) && (r3-r1 >= 16.f);

        int aidx = (y*64 + p2)*9 + k;
        int gi = n*ATOT + aidx;
        float sc = valid ? fg : -CUDART_INF_F;
        g_score[gi] = sc;
        g_roi[gi] = make_float4(r0,r1,r2,r3);
        // 31-bit key: batch bit 30 (batch 0 first, descending) | score bits
        // fg in (0,1) => bits < 0x40000000; invalid -> 0
        uint32_t u = valid ? __float_as_uint(fg) : 0u;
        g_key32[gi] = u | ((uint32_t)(1 - n) << 30);
        g_val[gi] = gi;
        if (n == 0) {
            out[OFF_ANCHOR + (size_t)aidx*4 + 0] = a0;
            out[OFF_ANCHOR + (size_t)aidx*4 + 1] = a1;
            out[OFF_ANCHOR + (size_t)aidx*4 + 2] = a2;
            out[OFF_ANCHOR + (size_t)aidx*4 + 3] = a3;
        }
    }
}

// ---------------------------------------------------------------------------
// Gather top-6000 boxes + scores after sort
// ---------------------------------------------------------------------------
__global__ void gather_kernel() {
    int t = blockIdx.x*256 + threadIdx.x;
    if (t >= NB*NPRE) return;
    int n = t/NPRE, i = t%NPRE;
    int gi = g_val_out[n*ATOT + i];
    g_boxes[t] = g_roi[gi];
    g_boxsc[t] = g_score[gi];
}

// ---------------------------------------------------------------------------
// NMS bitmask (upper triangle jb >= ib only — lower words never read)
// ---------------------------------------------------------------------------
__global__ __launch_bounds__(64) void mask_kernel() {
    int n  = blockIdx.z;
    int jb = blockIdx.x;
    int ib = blockIdx.y;
    if (jb < ib) return;
    int t  = threadIdx.x;

    __shared__ float4 cb[64];
    int j = jb*64 + t;
    cb[t] = (j < NPRE) ? g_boxes[n*NPRE + j] : make_float4(0.f,0.f,0.f,0.f);
    __syncthreads();

    int i = ib*64 + t;
    if (i >= NPRE) return;
    float4 bi = g_boxes[n*NPRE + i];
    float areai = (bi.z-bi.x)*(bi.w-bi.y);

    unsigned long long word = 0ull;
    int jmax = min(64, NPRE - jb*64);
    for (int jj=0; jj<jmax; jj++) {
        float4 bj = cb[jj];
        float areaj = (bj.z-bj.x)*(bj.w-bj.y);
        float ih = fmaxf(fminf(bi.z,bj.z) - fmaxf(bi.x,bj.x), 0.f);
        float iw = fmaxf(fminf(bi.w,bj.w) - fmaxf(bi.y,bj.y), 0.f);
        float inter = ih*iw;
        float iou = inter/(areai + areaj - inter + 1e-9f);
        if (iou > NMS_T) word |= (1ull << jj);
    }
    g_mask[((size_t)n*NPRE + i)*MASKW + jb] = word;
}

// ---------------------------------------------------------------------------
// Greedy NMS scan: one warp per batch, prefetched chunk loads
// ---------------------------------------------------------------------------
__global__ void scan_kernel() {
    int n = blockIdx.x;
    int lane = threadIdx.x;
    const unsigned FULL = 0xffffffffu;

    unsigned long long r0=0ull, r1=0ull, r2=0ull;
    int cnt = 0;
    const unsigned long long* mk = g_mask + (size_t)n*NPRE*MASKW;
    const float* sc = g_boxsc + n*NPRE;

    // preload chunk 0
    unsigned long long m0, m1;
    float s0, s1;
    {
        int i0 = lane, i1 = 32 + lane;
        m0 = mk[(size_t)i0*MASKW];
        m1 = mk[(size_t)i1*MASKW];
        s0 = sc[i0];
        s1 = sc[i1];
    }

    for (int ch=0; ch<MASKW; ch++) {
        // prefetch chunk ch+1
        unsigned long long nm0 = 0ull, nm1 = 0ull;
        float ns0 = -CUDART_INF_F, ns1 = -CUDART_INF_F;
        if (ch + 1 < MASKW) {
            int i0 = (ch+1)*64 + lane, i1 = i0 + 32;
            if (i0 < NPRE) { nm0 = mk[(size_t)i0*MASKW + ch + 1]; ns0 = sc[i0]; }
            if (i1 < NPRE) { nm1 = mk[(size_t)i1*MASKW + ch + 1]; ns1 = sc[i1]; }
        }

        unsigned inv0 = __ballot_sync(FULL, !isfinite(s0));
        unsigned inv1 = __ballot_sync(FULL, !isfinite(s1));
        unsigned long long W = (unsigned long long)inv0 | ((unsigned long long)inv1 << 32);

        int seg = ch >> 5, ln = ch & 31;
        unsigned long long rr = (seg==0) ? r0 : ((seg==1) ? r1 : r2);
        W |= __shfl_sync(FULL, rr, ln);

        unsigned long long keptb = 0ull;
        while (~W) {
            int p = __ffsll((long long)(~W)) - 1;
            keptb |= (1ull << p);
            if (lane == 0) g_kept[n*NPOST + cnt] = ch*64 + p;
            cnt++;
            if (cnt == NPOST) break;
            unsigned long long rw = __shfl_sync(FULL, (p<32) ? m0 : m1, p & 31);
            W |= rw;
        }
        if (cnt >= NPOST) break;

        unsigned long long kb = keptb;
        while (kb) {
            int p = __ffsll((long long)kb) - 1;
            kb &= kb - 1;
            size_t row = (size_t)(ch*64 + p)*MASKW;
            r0 |= mk[row + lane];
            r1 |= mk[row + 32 + lane];
            if (64 + lane < MASKW) r2 |= mk[row + 64 + lane];
        }

        m0 = nm0; m1 = nm1; s0 = ns0; s1 = ns1;
    }
    if (lane == 0) g_keptcnt[n] = cnt;
}

// ---------------------------------------------------------------------------
// Final outputs
// ---------------------------------------------------------------------------
__global__ void out_kernel(float* __restrict__ out) {
    int t = blockIdx.x*256 + threadIdx.x;
    if (t >= NB*NPOST) return;
    int n = t/NPOST, r = t%NPOST;
    int cnt = g_keptcnt[n];
    float4 b = make_float4(0.f,0.f,0.f,0.f);
    float vm = 0.f;
    if (r < cnt) {
        b = g_boxes[n*NPRE + g_kept[n*NPOST + r]];
        vm = 1.f;
    }
    out[OFF_ROIS + (size_t)t*4 + 0] = b.x;
    out[OFF_ROIS + (size_t)t*4 + 1] = b.y;
    out[OFF_ROIS + (size_t)t*4 + 2] = b.z;
    out[OFF_ROIS + (size_t)t*4 + 3] = b.w;
    out[OFF_RIDX + t]  = (float)n;
    out[OFF_VMASK + t] = vm;
}

// ---------------------------------------------------------------------------
// Launch
// ---------------------------------------------------------------------------
extern "C" void kernel_launch(void* const* d_in, const int* in_sizes, int n_in,
                              void* d_out, int out_size) {
    const float* x  = (const float*)d_in[0];
    const float* w  = (const float*)d_in[1];
    const float* b  = (const float*)d_in[2];
    const float* sw = (const float*)d_in[3];
    const float* sb = (const float*)d_in[4];
    const float* lw = (const float*)d_in[5];
    const float* lb = (const float*)d_in[6];
    float* out = (float*)d_out;

    cudaFuncSetAttribute(mma_conv_kernel,
                         cudaFuncAttributeMaxDynamicSharedMemorySize, SMEM_DYN);

    split_x_kernel<<<dim3(128, 16, 2), dim3(32, 8)>>>(x);
    split_w_kernel<<<(KTAP*CIN*CIN + 255)/256, 256>>>(w);
    mma_conv_kernel<<<dim3(64, 4), 256, SMEM_DYN>>>(b);
    heads_part_kernel<<<dim3(64, 2, NQ), 256>>>(sw, lw);
    finalize_kernel<<<dim3(64, 2), 256>>>(sb, lb, d_in[7], d_in[8], out);

    void* tmp;
    uint32_t *ki, *ko;
    int *vi, *vo;
    cudaGetSymbolAddress(&tmp, g_cub_temp);
    cudaGetSymbolAddress((void**)&ki, g_key32);
    cudaGetSymbolAddress((void**)&ko, g_key32_out);
    cudaGetSymbolAddress((void**)&vi, g_val);
    cudaGetSymbolAddress((void**)&vo, g_val_out);

    {
        size_t tb = 0;
        cub::DeviceRadixSort::SortPairsDescending(nullptr, tb,
            ki, ko, vi, vo, NB*ATOT, 0, 31, (cudaStream_t)0);
        if (tb <= sizeof(g_cub_temp)) {
            cub::DeviceRadixSort::SortPairsDescending(tmp, tb,
                ki, ko, vi, vo, NB*ATOT, 0, 31, (cudaStream_t)0);
        }
    }

    gather_kernel<<<(NB*NPRE + 255)/256, 256>>>();
    mask_kernel<<<dim3(MASKW, MASKW, NB), 64>>>();
    scan_kernel<<<NB, 32>>>();
    out_kernel<<<(NB*NPOST + 255)/256, 256>>>(out);
}